// round 8
// baseline (speedup 1.0000x reference)
#include <cuda_runtime.h>
#include <cuda_bf16.h>
#include <cstdint>

// ---------------------------------------------------------------------------
// PhaseTracker: encode(+evolve fused) -> HMMA bf16-split GEMM -> greedy
// ---------------------------------------------------------------------------

#define N_DET   4096
#define DIM     128
#define HID     64
#define NOSC    28
#define KGEMM   192          // 3 blocks of 56 (hi|hi|lo vs hi|lo|hi) padded
#define KTILES  11           // k < 176 (data ends at 168, [168,176) zeroed)
#define TWO_PI_F 6.283185307179586f
#define INV_2PI  0.15915494309189535f
#define DENOM_F  28.000010583006244f   // (sqrt(28)+1e-6)^2

__device__ __align__(16) __nv_bfloat16 g_Abf[N_DET * KGEMM];  // [hi56|hi56|lo56|pad]
__device__ __align__(16) __nv_bfloat16 g_Bbf[N_DET * KGEMM];  // [hi56|lo56|hi56|pad]
__device__ unsigned long long g_rowbest[N_DET];
__device__ unsigned long long g_colbest[N_DET];

__device__ __forceinline__ float mod2pi(float v) {
    return v - floorf(v * INV_2PI) * TWO_PI_F;
}
__device__ __forceinline__ float softplusf(float x) {
    return fmaxf(x, 0.0f) + log1pf(expf(-fabsf(x)));
}
__device__ __forceinline__ unsigned ordf(float x) {
    unsigned u = __float_as_uint(x);
    return (u & 0x80000000u) ? ~u : (u | 0x80000000u);
}
__device__ __forceinline__ void bf16split(float v, __nv_bfloat16& hi, __nv_bfloat16& lo) {
    hi = __float2bfloat16_rn(v);
    lo = __float2bfloat16_rn(v - __bfloat162float(hi));
}
__device__ __forceinline__ uint32_t smem_u32(const void* p) {
    uint32_t a;
    asm("{ .reg .u64 t; cvta.to.shared.u64 t, %1; cvt.u32.u64 %0, t; }" : "=r"(a) : "l"(p));
    return a;
}
__device__ __forceinline__ void ldm_x4(uint32_t* r, uint32_t addr) {
    asm volatile("ldmatrix.sync.aligned.m8n8.x4.shared.b16 {%0,%1,%2,%3}, [%4];"
                 : "=r"(r[0]), "=r"(r[1]), "=r"(r[2]), "=r"(r[3]) : "r"(addr));
}
__device__ __forceinline__ void ldm_x2(uint32_t* r, uint32_t addr) {
    asm volatile("ldmatrix.sync.aligned.m8n8.x2.shared.b16 {%0,%1}, [%2];"
                 : "=r"(r[0]), "=r"(r[1]) : "r"(addr));
}
__device__ __forceinline__ void mma16816(float* c, const uint32_t* a, const uint32_t* b) {
    asm volatile("mma.sync.aligned.m16n8k16.row.col.f32.bf16.bf16.f32 "
                 "{%0,%1,%2,%3}, {%4,%5,%6,%7}, {%8,%9}, {%0,%1,%2,%3};"
                 : "+f"(c[0]), "+f"(c[1]), "+f"(c[2]), "+f"(c[3])
                 : "r"(a[0]), "r"(a[1]), "r"(a[2]), "r"(a[3]), "r"(b[0]), "r"(b[1]));
}

// ---------------------------------------------------------------------------
// Encode with fused init + fused evolve.
// ---------------------------------------------------------------------------
#define ENC_W1STR 132
#define ENC_W2STR 68
#define ENC_SMEM_FLOATS (2*HID*ENC_W1STR + 2*NOSC*ENC_W2STR + 512 + 512 + 128)

__global__ __launch_bounds__(256, 2)
void encode_kernel(const float* __restrict__ det_t, const float* __restrict__ det_t1,
                   const float* __restrict__ Wp1, const float* __restrict__ bp1,
                   const float* __restrict__ Wp2, const float* __restrict__ bp2,
                   const float* __restrict__ Wa1, const float* __restrict__ ba1,
                   const float* __restrict__ Wa2, const float* __restrict__ ba2) {
    extern __shared__ float sm[];
    float* wp1T = sm;
    float* wa1T = wp1T + HID * ENC_W1STR;
    float* wp2T = wa1T + HID * ENC_W1STR;
    float* wa2T = wp2T + NOSC * ENC_W2STR;
    float* xs   = wa2T + NOSC * ENC_W2STR;     // 4 x 128
    float* hs   = xs + 512;                    // 4 x 128
    float* amps = hs + 512;                    // 4 x 32

    int tid = threadIdx.x;

    // fused init (blocks 0..15): zero rowbest/colbest + K pads
    if (blockIdx.x < 16) {
        int i = blockIdx.x * 256 + tid;
        g_rowbest[i] = 0ull; g_colbest[i] = 0ull;
        uint4 z = make_uint4(0, 0, 0, 0);
        uint4* pa = (uint4*)((char*)g_Abf + (size_t)i * 384 + 336);
        uint4* pb = (uint4*)((char*)g_Bbf + (size_t)i * 384 + 336);
        pa[0] = z; pa[1] = z; pa[2] = z;
        pb[0] = z; pb[1] = z; pb[2] = z;
    }

    for (int idx = tid; idx < DIM * HID; idx += 256) {
        int k = idx >> 6, j = idx & 63;
        wp1T[j * ENC_W1STR + k] = Wp1[idx];
        wa1T[j * ENC_W1STR + k] = Wa1[idx];
    }
    for (int idx = tid; idx < HID * NOSC; idx += 256) {
        int k = idx / NOSC, j = idx % NOSC;
        wp2T[j * ENC_W2STR + k] = Wp2[idx];
        wa2T[j * ENC_W2STR + k] = Wa2[idx];
    }

    const int quad = tid >> 7;
    const int t    = tid & 127;
    const int r0 = 2 * quad, r1 = r0 + 1;

    for (int it = 0; it < 8; ++it) {
        int rowbase = blockIdx.x * 32 + it * 4;
        bool isT = rowbase < N_DET;
        const float* X = isT ? (det_t + (size_t)rowbase * DIM)
                             : (det_t1 + (size_t)(rowbase - N_DET) * DIM);
        __syncthreads();
        if (tid < 128) {
            ((float4*)xs)[tid] = ((const float4*)X)[tid];
        }
        __syncthreads();

        // ---- layer 1 ----
        {
            bool doAmp = (t >= 64);
            if (!doAmp || isT) {
                int j = doAmp ? (t - 64) : t;
                const float4* w4 = (const float4*)(doAmp ? &wa1T[j * ENC_W1STR]
                                                         : &wp1T[j * ENC_W1STR]);
                const float4* x0 = (const float4*)(xs + r0 * 128);
                const float4* x1 = (const float4*)(xs + r1 * 128);
                float b = doAmp ? ba1[j] : bp1[j];
                float a0 = b, a1 = b, c0 = 0.0f, c1 = 0.0f;
                #pragma unroll
                for (int k4 = 0; k4 < 32; k4 += 2) {
                    float4 w = w4[k4];
                    float4 xa = x0[k4], xb = x1[k4];
                    a0 += w.x * xa.x + w.y * xa.y + w.z * xa.z + w.w * xa.w;
                    a1 += w.x * xb.x + w.y * xb.y + w.z * xb.z + w.w * xb.w;
                    float4 w2 = w4[k4 + 1];
                    float4 xc = x0[k4 + 1], xd = x1[k4 + 1];
                    c0 += w2.x * xc.x + w2.y * xc.y + w2.z * xc.z + w2.w * xc.w;
                    c1 += w2.x * xd.x + w2.y * xd.y + w2.z * xd.z + w2.w * xd.w;
                }
                hs[r0 * 128 + t] = fmaxf(a0 + c0, 0.0f);
                hs[r1 * 128 + t] = fmaxf(a1 + c1, 0.0f);
            }
        }
        __syncthreads();

        // ---- layer 2 ----
        int lane = t & 31, wgrp = t >> 5;
        float ph0 = 0.0f, ph1 = 0.0f;
        if (wgrp == 0 && lane < NOSC) {               // phase head
            const float4* w4 = (const float4*)&wp2T[lane * ENC_W2STR];
            const float4* h0 = (const float4*)(hs + r0 * 128);
            const float4* h1 = (const float4*)(hs + r1 * 128);
            float b = bp2[lane];
            float p0 = b, p1 = b, q0 = 0.0f, q1 = 0.0f;
            #pragma unroll
            for (int k4 = 0; k4 < 16; k4 += 2) {
                float4 w = w4[k4];
                float4 ha = h0[k4], hb = h1[k4];
                p0 += w.x * ha.x + w.y * ha.y + w.z * ha.z + w.w * ha.w;
                p1 += w.x * hb.x + w.y * hb.y + w.z * hb.z + w.w * hb.w;
                float4 w2 = w4[k4 + 1];
                float4 hc = h0[k4 + 1], hd = h1[k4 + 1];
                q0 += w2.x * hc.x + w2.y * hc.y + w2.z * hc.z + w2.w * hc.w;
                q1 += w2.x * hd.x + w2.y * hd.y + w2.z * hd.z + w2.w * hd.w;
            }
            ph0 = mod2pi(p0 + q0); ph1 = mod2pi(p1 + q1);
            if (!isT) {
                // B' row layout: [cos_hi28 sin_hi28 | cos_lo28 sin_lo28 | cos_hi28 sin_hi28]
                int cc0 = rowbase - N_DET + r0, cc1 = cc0 + 1;
                float cv0 = cosf(ph0), sv0 = sinf(ph0);
                float cv1 = cosf(ph1), sv1 = sinf(ph1);
                __nv_bfloat16 chi, clo, shi, slo;
                __nv_bfloat16* br;
                br = g_Bbf + (size_t)cc0 * KGEMM;
                bf16split(cv0, chi, clo); bf16split(sv0, shi, slo);
                br[lane] = chi;       br[28 + lane] = shi;
                br[56 + lane] = clo;  br[84 + lane] = slo;
                br[112 + lane] = chi; br[140 + lane] = shi;
                br = g_Bbf + (size_t)cc1 * KGEMM;
                bf16split(cv1, chi, clo); bf16split(sv1, shi, slo);
                br[lane] = chi;       br[28 + lane] = shi;
                br[56 + lane] = clo;  br[84 + lane] = slo;
                br[112 + lane] = chi; br[140 + lane] = shi;
            }
        } else if (wgrp == 1 && lane < NOSC && isT) { // amp head -> smem
            const float4* w4 = (const float4*)&wa2T[lane * ENC_W2STR];
            const float4* h0 = (const float4*)(hs + r0 * 128 + 64);
            const float4* h1 = (const float4*)(hs + r1 * 128 + 64);
            float b = ba2[lane];
            float p0 = b, p1 = b, q0 = 0.0f, q1 = 0.0f;
            #pragma unroll
            for (int k4 = 0; k4 < 16; k4 += 2) {
                float4 w = w4[k4];
                float4 ha = h0[k4], hb = h1[k4];
                p0 += w.x * ha.x + w.y * ha.y + w.z * ha.z + w.w * ha.w;
                p1 += w.x * hb.x + w.y * hb.y + w.z * hb.z + w.w * hb.w;
                float4 w2 = w4[k4 + 1];
                float4 hc = h0[k4 + 1], hd = h1[k4 + 1];
                q0 += w2.x * hc.x + w2.y * hc.y + w2.z * hc.z + w2.w * hc.w;
                q1 += w2.x * hd.x + w2.y * hd.y + w2.z * hd.z + w2.w * hd.w;
            }
            amps[r0 * 32 + lane] = softplusf(p0 + q0);
            amps[r1 * 32 + lane] = softplusf(p1 + q1);
        }
        __syncthreads();

        // ---- fused evolve (phase warps only, t rows only) ----
        if (wgrp == 0 && isT) {
            bool act = lane < NOSC;
            float am0 = act ? amps[r0 * 32 + lane] : 0.0f;
            float am1 = act ? amps[r1 * 32 + lane] : 0.0f;
            float omega = TWO_PI_F * (lane < 4 ? 2.0f : (lane < 12 ? 6.0f : 40.0f));
            #pragma unroll
            for (int s = 0; s < 5; ++s) {
                float c0 = act ? cosf(ph0) : 0.0f;
                float s0 = act ? sinf(ph0) : 0.0f;
                float c1 = act ? cosf(ph1) : 0.0f;
                float s1 = act ? sinf(ph1) : 0.0f;
                float sc0 = c0, ss0 = s0, sc1 = c1, ss1 = s1;
                #pragma unroll
                for (int off = 16; off; off >>= 1) {
                    sc0 += __shfl_down_sync(0xFFFFFFFFu, sc0, off);
                    ss0 += __shfl_down_sync(0xFFFFFFFFu, ss0, off);
                    sc1 += __shfl_down_sync(0xFFFFFFFFu, sc1, off);
                    ss1 += __shfl_down_sync(0xFFFFFFFFu, ss1, off);
                }
                sc0 = __shfl_sync(0xFFFFFFFFu, sc0, 0);
                ss0 = __shfl_sync(0xFFFFFFFFu, ss0, 0);
                sc1 = __shfl_sync(0xFFFFFFFFu, sc1, 0);
                ss1 = __shfl_sync(0xFFFFFFFFu, ss1, 0);
                float coup0 = (ss0 / 28.0f) * c0 - (sc0 / 28.0f) * s0;
                float coup1 = (ss1 / 28.0f) * c1 - (sc1 / 28.0f) * s1;
                ph0 = mod2pi(ph0 + 0.01f * (omega + am0 * coup0));
                ph1 = mod2pi(ph1 + 0.01f * (omega + am1 * coup1));
            }
            if (act) {
                // A' row layout: [cos_hi28 sin_hi28 | cos_hi28 sin_hi28 | cos_lo28 sin_lo28]
                int gr0 = rowbase + r0, gr1 = rowbase + r1;
                float c, sn;
                __nv_bfloat16 chi, clo, shi, slo;
                __nv_bfloat16* ar;
                c = cosf(ph0); sn = sinf(ph0);
                bf16split(c, chi, clo); bf16split(sn, shi, slo);
                ar = g_Abf + (size_t)gr0 * KGEMM;
                ar[lane] = chi;       ar[28 + lane] = shi;
                ar[56 + lane] = chi;  ar[84 + lane] = shi;
                ar[112 + lane] = clo; ar[140 + lane] = slo;
                c = cosf(ph1); sn = sinf(ph1);
                bf16split(c, chi, clo); bf16split(sn, shi, slo);
                ar = g_Abf + (size_t)gr1 * KGEMM;
                ar[lane] = chi;       ar[28 + lane] = shi;
                ar[56 + lane] = chi;  ar[84 + lane] = shi;
                ar[112 + lane] = clo; ar[140 + lane] = slo;
            }
        }
    }
}

// ---------------------------------------------------------------------------
// HMMA GEMM: 128x128 tile/CTA, 512 threads / 16 warps (4x4), warp = 32x32.
// SMEM rows 368 B (23x16, odd -> conflict-free ldmatrix). Fused rowbest.
// ---------------------------------------------------------------------------
#define GT_ROWB   368
#define GT_TILE   (128 * GT_ROWB)           // 47104
#define GT_SMEM_TOTAL (2 * GT_TILE)         // 94208

__global__ __launch_bounds__(512, 1)
void gemm_kernel(float* __restrict__ sim) {
    extern __shared__ char smg[];
    const int tid = threadIdx.x;
    const int lane = tid & 31;
    const int w = tid >> 5;
    const int warpRow = w >> 2;       // 0..3  (32 rows each)
    const int warpCol = w & 3;        // 0..3  (32 cols each)
    uint32_t smA = smem_u32(smg);
    uint32_t smB = smA + GT_TILE;

    // ---- stage tiles: 22 chunks of 16B per row (K<176) ----
    {
        const uint4* srcA = (const uint4*)(g_Abf + (size_t)blockIdx.y * 128 * KGEMM);
        const uint4* srcB = (const uint4*)(g_Bbf + (size_t)blockIdx.x * 128 * KGEMM);
        #pragma unroll
        for (int i = 0; i < 11; ++i) {
            int idx = tid + i * 512;          // 0..5631 over both tiles
            int half = idx >= 2816;
            int e = half ? idx - 2816 : idx;  // 0..2815
            int r = e / 22, q = e - r * 22;
            int off = r * GT_ROWB + q * 16;
            if (half) *(uint4*)(smg + GT_TILE + off) = srcB[r * 24 + q];
            else      *(uint4*)(smg + off) = srcA[r * 24 + q];
        }
    }
    __syncthreads();

    float acc[2][4][4];
    #pragma unroll
    for (int mt = 0; mt < 2; ++mt)
        #pragma unroll
        for (int nt = 0; nt < 4; ++nt)
            #pragma unroll
            for (int e = 0; e < 4; ++e) acc[mt][nt][e] = 0.0f;

    const uint32_t aBase = smA + (warpRow * 32 + (lane & 15)) * GT_ROWB + (lane >> 4) * 16;
    const uint32_t bBase = smB + (warpCol * 32 + (lane & 7)) * GT_ROWB + ((lane >> 3) & 1) * 16;

    #pragma unroll
    for (int kt = 0; kt < KTILES; ++kt) {
        uint32_t af[2][4], bf[4][2];
        #pragma unroll
        for (int mt = 0; mt < 2; ++mt)
            ldm_x4(af[mt], aBase + mt * 16 * GT_ROWB + kt * 32);
        #pragma unroll
        for (int nt = 0; nt < 4; ++nt)
            ldm_x2(bf[nt], bBase + nt * 8 * GT_ROWB + kt * 32);
        #pragma unroll
        for (int mt = 0; mt < 2; ++mt)
            #pragma unroll
            for (int nt = 0; nt < 4; ++nt)
                mma16816(acc[mt][nt], af[mt], bf[nt]);
    }

    // ---- epilogue: scale, store, fused rowbest ----
    const float invden = 1.0f / DENOM_F;
    const int g = lane >> 2, tq = lane & 3;
    const int rowg = blockIdx.y * 128 + warpRow * 32 + g;
    const int colg = blockIdx.x * 128 + warpCol * 32 + tq * 2;

    #pragma unroll
    for (int mt = 0; mt < 2; ++mt) {
        int r0 = rowg + mt * 16;
        int r1 = r0 + 8;
        unsigned long long best0 = 0ull, best1 = 0ull;
        #pragma unroll
        for (int nt = 0; nt < 4; ++nt) {
            int col = colg + nt * 8;
            float2 v0, v1;
            v0.x = acc[mt][nt][0] * invden; v0.y = acc[mt][nt][1] * invden;
            v1.x = acc[mt][nt][2] * invden; v1.y = acc[mt][nt][3] * invden;
            *(float2*)(sim + (size_t)r0 * N_DET + col) = v0;
            *(float2*)(sim + (size_t)r1 * N_DET + col) = v1;
            unsigned long long k;
            k = ((unsigned long long)ordf(v0.x) << 32) | (unsigned)(~(unsigned)col);
            if (k > best0) best0 = k;
            k = ((unsigned long long)ordf(v0.y) << 32) | (unsigned)(~(unsigned)(col + 1));
            if (k > best0) best0 = k;
            k = ((unsigned long long)ordf(v1.x) << 32) | (unsigned)(~(unsigned)col);
            if (k > best1) best1 = k;
            k = ((unsigned long long)ordf(v1.y) << 32) | (unsigned)(~(unsigned)(col + 1));
            if (k > best1) best1 = k;
        }
        #pragma unroll
        for (int off = 1; off < 4; off <<= 1) {
            unsigned long long o0 = __shfl_xor_sync(0xFFFFFFFFu, best0, off);
            unsigned long long o1 = __shfl_xor_sync(0xFFFFFFFFu, best1, off);
            if (o0 > best0) best0 = o0;
            if (o1 > best1) best1 = o1;
        }
        if (tq == 0) {
            atomicMax(&g_rowbest[r0], best0);
            atomicMax(&g_rowbest[r1], best1);
        }
    }
}

// ---------------------------------------------------------------------------
// Parallel greedy match (exact equivalent of the sequential scan).
// ---------------------------------------------------------------------------
__global__ void claim_kernel() {
    int i = blockIdx.x * blockDim.x + threadIdx.x;
    if (i >= N_DET) return;
    const unsigned ORD_THR = __float_as_uint(0.3f) | 0x80000000u;
    unsigned long long rb = g_rowbest[i];
    unsigned ordsim = (unsigned)(rb >> 32);
    if (ordsim > ORD_THR) {
        unsigned j = ~(unsigned)rb;
        unsigned long long claimkey = (rb & 0xFFFFFFFF00000000ull) | (unsigned)(~(unsigned)i);
        atomicMax(&g_colbest[j], claimkey);
    }
}

__global__ void resolve_kernel(float* __restrict__ matches) {
    int i = blockIdx.x * blockDim.x + threadIdx.x;
    if (i >= N_DET) return;
    const unsigned ORD_THR = __float_as_uint(0.3f) | 0x80000000u;
    unsigned long long rb = g_rowbest[i];
    unsigned ordsim = (unsigned)(rb >> 32);
    float m = -1.0f;
    if (ordsim > ORD_THR) {
        unsigned j = ~(unsigned)rb;
        unsigned long long claimkey = (rb & 0xFFFFFFFF00000000ull) | (unsigned)(~(unsigned)i);
        if (g_colbest[j] == claimkey) m = (float)j;
    }
    matches[i] = m;
}

// ---------------------------------------------------------------------------
extern "C" void kernel_launch(void* const* d_in, const int* in_sizes, int n_in,
                              void* d_out, int out_size) {
    const float* det_t  = (const float*)d_in[0];
    const float* det_t1 = (const float*)d_in[1];
    const float* Wp1 = (const float*)d_in[2];
    const float* bp1 = (const float*)d_in[3];
    const float* Wp2 = (const float*)d_in[4];
    const float* bp2 = (const float*)d_in[5];
    const float* Wa1 = (const float*)d_in[6];
    const float* ba1 = (const float*)d_in[7];
    const float* Wa2 = (const float*)d_in[8];
    const float* ba2 = (const float*)d_in[9];
    float* out = (float*)d_out;                 // [0,4096): matches, then sim

    cudaFuncSetAttribute(encode_kernel, cudaFuncAttributeMaxDynamicSharedMemorySize,
                         ENC_SMEM_FLOATS * 4);
    cudaFuncSetAttribute(gemm_kernel, cudaFuncAttributeMaxDynamicSharedMemorySize,
                         GT_SMEM_TOTAL);

    encode_kernel<<<256, 256, ENC_SMEM_FLOATS * 4>>>(det_t, det_t1,
                                                     Wp1, bp1, Wp2, bp2,
                                                     Wa1, ba1, Wa2, ba2);
    gemm_kernel<<<dim3(32, 32), 512, GT_SMEM_TOTAL>>>(out + N_DET);
    claim_kernel<<<16, 256>>>();
    resolve_kernel<<<16, 256>>>(out);
}

// round 9
// speedup vs baseline: 1.2161x; 1.2161x over previous
#include <cuda_runtime.h>
#include <cuda_bf16.h>
#include <cstdint>

// ---------------------------------------------------------------------------
// PhaseTracker: encode -> evolve -> HMMA bf16-split GEMM (512thr) -> greedy
// ---------------------------------------------------------------------------

#define N_DET   4096
#define DIM     128
#define HID     64
#define NOSC    28
#define KGEMM   192          // 3 blocks of 56 (hi|hi|lo vs hi|lo|hi) padded
#define KTILES  11           // k < 176 (data ends at 168, [168,176) zeroed)
#define TWO_PI_F 6.283185307179586f
#define INV_2PI  0.15915494309189535f
#define DENOM_F  28.000010583006244f   // (sqrt(28)+1e-6)^2

__device__ float g_phase[N_DET * NOSC];
__device__ float g_amp[N_DET * NOSC];
__device__ __align__(16) __nv_bfloat16 g_Abf[N_DET * KGEMM];  // [hi56|hi56|lo56|pad]
__device__ __align__(16) __nv_bfloat16 g_Bbf[N_DET * KGEMM];  // [hi56|lo56|hi56|pad]
__device__ unsigned long long g_rowbest[N_DET];
__device__ unsigned long long g_colbest[N_DET];

__device__ __forceinline__ float mod2pi(float v) {
    return v - floorf(v * INV_2PI) * TWO_PI_F;
}
__device__ __forceinline__ float softplusf(float x) {
    return fmaxf(x, 0.0f) + log1pf(expf(-fabsf(x)));
}
__device__ __forceinline__ unsigned ordf(float x) {
    unsigned u = __float_as_uint(x);
    return (u & 0x80000000u) ? ~u : (u | 0x80000000u);
}
__device__ __forceinline__ void bf16split(float v, __nv_bfloat16& hi, __nv_bfloat16& lo) {
    hi = __float2bfloat16_rn(v);
    lo = __float2bfloat16_rn(v - __bfloat162float(hi));
}
__device__ __forceinline__ uint32_t smem_u32(const void* p) {
    uint32_t a;
    asm("{ .reg .u64 t; cvta.to.shared.u64 t, %1; cvt.u32.u64 %0, t; }" : "=r"(a) : "l"(p));
    return a;
}
__device__ __forceinline__ void ldm_x4(uint32_t* r, uint32_t addr) {
    asm volatile("ldmatrix.sync.aligned.m8n8.x4.shared.b16 {%0,%1,%2,%3}, [%4];"
                 : "=r"(r[0]), "=r"(r[1]), "=r"(r[2]), "=r"(r[3]) : "r"(addr));
}
__device__ __forceinline__ void ldm_x2(uint32_t* r, uint32_t addr) {
    asm volatile("ldmatrix.sync.aligned.m8n8.x2.shared.b16 {%0,%1}, [%2];"
                 : "=r"(r[0]), "=r"(r[1]) : "r"(addr));
}
__device__ __forceinline__ void mma16816(float* c, const uint32_t* a, const uint32_t* b) {
    asm volatile("mma.sync.aligned.m16n8k16.row.col.f32.bf16.bf16.f32 "
                 "{%0,%1,%2,%3}, {%4,%5,%6,%7}, {%8,%9}, {%0,%1,%2,%3};"
                 : "+f"(c[0]), "+f"(c[1]), "+f"(c[2]), "+f"(c[3])
                 : "r"(a[0]), "r"(a[1]), "r"(a[2]), "r"(a[3]), "r"(b[0]), "r"(b[1]));
}

// ---------------------------------------------------------------------------
__global__ void init_kernel() {
    int i = blockIdx.x * blockDim.x + threadIdx.x;
    if (i < N_DET) {
        g_rowbest[i] = 0ull; g_colbest[i] = 0ull;
        uint4 z = make_uint4(0, 0, 0, 0);
        uint4* pa = (uint4*)((char*)g_Abf + (size_t)i * 384 + 336);
        uint4* pb = (uint4*)((char*)g_Bbf + (size_t)i * 384 + 336);
        pa[0] = z; pa[1] = z; pa[2] = z;
        pb[0] = z; pb[1] = z; pb[2] = z;
    }
}

// ---------------------------------------------------------------------------
// Encode (R7-proven): two rows per weight read.
// ---------------------------------------------------------------------------
#define ENC_W1STR 132
#define ENC_W2STR 68
#define ENC_SMEM_FLOATS (2*HID*ENC_W1STR + 2*NOSC*ENC_W2STR + 512 + 512)

__global__ __launch_bounds__(256, 2)
void encode_kernel(const float* __restrict__ det_t, const float* __restrict__ det_t1,
                   const float* __restrict__ Wp1, const float* __restrict__ bp1,
                   const float* __restrict__ Wp2, const float* __restrict__ bp2,
                   const float* __restrict__ Wa1, const float* __restrict__ ba1,
                   const float* __restrict__ Wa2, const float* __restrict__ ba2) {
    extern __shared__ float sm[];
    float* wp1T = sm;
    float* wa1T = wp1T + HID * ENC_W1STR;
    float* wp2T = wa1T + HID * ENC_W1STR;
    float* wa2T = wp2T + NOSC * ENC_W2STR;
    float* xs   = wa2T + NOSC * ENC_W2STR;     // 4 x 128
    float* hs   = xs + 512;                    // 4 x 128

    int tid = threadIdx.x;
    for (int idx = tid; idx < DIM * HID; idx += 256) {
        int k = idx >> 6, j = idx & 63;
        wp1T[j * ENC_W1STR + k] = Wp1[idx];
        wa1T[j * ENC_W1STR + k] = Wa1[idx];
    }
    for (int idx = tid; idx < HID * NOSC; idx += 256) {
        int k = idx / NOSC, j = idx % NOSC;
        wp2T[j * ENC_W2STR + k] = Wp2[idx];
        wa2T[j * ENC_W2STR + k] = Wa2[idx];
    }

    const int quad = tid >> 7;
    const int t    = tid & 127;
    const int r0 = 2 * quad, r1 = r0 + 1;

    for (int it = 0; it < 8; ++it) {
        int rowbase = blockIdx.x * 32 + it * 4;
        bool isT = rowbase < N_DET;
        const float* X = isT ? (det_t + (size_t)rowbase * DIM)
                             : (det_t1 + (size_t)(rowbase - N_DET) * DIM);
        __syncthreads();
        if (tid < 128) {
            ((float4*)xs)[tid] = ((const float4*)X)[tid];
        }
        __syncthreads();

        {
            bool doAmp = (t >= 64);
            if (!doAmp || isT) {
                int j = doAmp ? (t - 64) : t;
                const float4* w4 = (const float4*)(doAmp ? &wa1T[j * ENC_W1STR]
                                                         : &wp1T[j * ENC_W1STR]);
                const float4* x0 = (const float4*)(xs + r0 * 128);
                const float4* x1 = (const float4*)(xs + r1 * 128);
                float b = doAmp ? ba1[j] : bp1[j];
                float a0 = b, a1 = b, c0 = 0.0f, c1 = 0.0f;
                #pragma unroll
                for (int k4 = 0; k4 < 32; k4 += 2) {
                    float4 w = w4[k4];
                    float4 xa = x0[k4], xb = x1[k4];
                    a0 += w.x * xa.x + w.y * xa.y + w.z * xa.z + w.w * xa.w;
                    a1 += w.x * xb.x + w.y * xb.y + w.z * xb.z + w.w * xb.w;
                    float4 w2 = w4[k4 + 1];
                    float4 xc = x0[k4 + 1], xd = x1[k4 + 1];
                    c0 += w2.x * xc.x + w2.y * xc.y + w2.z * xc.z + w2.w * xc.w;
                    c1 += w2.x * xd.x + w2.y * xd.y + w2.z * xd.z + w2.w * xd.w;
                }
                hs[r0 * 128 + t] = fmaxf(a0 + c0, 0.0f);
                hs[r1 * 128 + t] = fmaxf(a1 + c1, 0.0f);
            }
        }
        __syncthreads();

        int lane = t & 31, wgrp = t >> 5;
        if (wgrp == 0 && lane < NOSC) {               // phase head
            const float4* w4 = (const float4*)&wp2T[lane * ENC_W2STR];
            const float4* h0 = (const float4*)(hs + r0 * 128);
            const float4* h1 = (const float4*)(hs + r1 * 128);
            float b = bp2[lane];
            float p0 = b, p1 = b, q0 = 0.0f, q1 = 0.0f;
            #pragma unroll
            for (int k4 = 0; k4 < 16; k4 += 2) {
                float4 w = w4[k4];
                float4 ha = h0[k4], hb = h1[k4];
                p0 += w.x * ha.x + w.y * ha.y + w.z * ha.z + w.w * ha.w;
                p1 += w.x * hb.x + w.y * hb.y + w.z * hb.z + w.w * hb.w;
                float4 w2 = w4[k4 + 1];
                float4 hc = h0[k4 + 1], hd = h1[k4 + 1];
                q0 += w2.x * hc.x + w2.y * hc.y + w2.z * hc.z + w2.w * hc.w;
                q1 += w2.x * hd.x + w2.y * hd.y + w2.z * hd.z + w2.w * hd.w;
            }
            float ph0 = mod2pi(p0 + q0), ph1 = mod2pi(p1 + q1);
            int gr0 = rowbase + r0, gr1 = rowbase + r1;
            if (isT) {
                g_phase[gr0 * NOSC + lane] = ph0;
                g_phase[gr1 * NOSC + lane] = ph1;
            } else {
                // B' row layout: [cos_hi28 sin_hi28 | cos_lo28 sin_lo28 | cos_hi28 sin_hi28]
                int cc0 = gr0 - N_DET, cc1 = gr1 - N_DET;
                float cv0 = cosf(ph0), sv0 = sinf(ph0);
                float cv1 = cosf(ph1), sv1 = sinf(ph1);
                __nv_bfloat16 chi, clo, shi, slo;
                __nv_bfloat16* br;
                br = g_Bbf + (size_t)cc0 * KGEMM;
                bf16split(cv0, chi, clo); bf16split(sv0, shi, slo);
                br[lane] = chi;       br[28 + lane] = shi;
                br[56 + lane] = clo;  br[84 + lane] = slo;
                br[112 + lane] = chi; br[140 + lane] = shi;
                br = g_Bbf + (size_t)cc1 * KGEMM;
                bf16split(cv1, chi, clo); bf16split(sv1, shi, slo);
                br[lane] = chi;       br[28 + lane] = shi;
                br[56 + lane] = clo;  br[84 + lane] = slo;
                br[112 + lane] = chi; br[140 + lane] = shi;
            }
        } else if (wgrp == 1 && lane < NOSC && isT) { // amp head
            const float4* w4 = (const float4*)&wa2T[lane * ENC_W2STR];
            const float4* h0 = (const float4*)(hs + r0 * 128 + 64);
            const float4* h1 = (const float4*)(hs + r1 * 128 + 64);
            float b = ba2[lane];
            float p0 = b, p1 = b, q0 = 0.0f, q1 = 0.0f;
            #pragma unroll
            for (int k4 = 0; k4 < 16; k4 += 2) {
                float4 w = w4[k4];
                float4 ha = h0[k4], hb = h1[k4];
                p0 += w.x * ha.x + w.y * ha.y + w.z * ha.z + w.w * ha.w;
                p1 += w.x * hb.x + w.y * hb.y + w.z * hb.z + w.w * hb.w;
                float4 w2 = w4[k4 + 1];
                float4 hc = h0[k4 + 1], hd = h1[k4 + 1];
                q0 += w2.x * hc.x + w2.y * hc.y + w2.z * hc.z + w2.w * hc.w;
                q1 += w2.x * hd.x + w2.y * hd.y + w2.z * hd.z + w2.w * hd.w;
            }
            g_amp[(rowbase + r0) * NOSC + lane] = softplusf(p0 + q0);
            g_amp[(rowbase + r1) * NOSC + lane] = softplusf(p1 + q1);
        }
    }
}

// ---------------------------------------------------------------------------
// Evolve (R7-proven): 5 Kuramoto steps, one warp per row.
// ---------------------------------------------------------------------------
__global__ void evolve_kernel() {
    int gw   = (blockIdx.x * blockDim.x + threadIdx.x) >> 5;
    int lane = threadIdx.x & 31;
    if (gw >= N_DET) return;
    bool act = lane < NOSC;

    float ph = act ? g_phase[gw * NOSC + lane] : 0.0f;
    float am = act ? g_amp[gw * NOSC + lane] : 0.0f;
    float omega = TWO_PI_F * (lane < 4 ? 2.0f : (lane < 12 ? 6.0f : 40.0f));

    #pragma unroll
    for (int s = 0; s < 5; ++s) {
        float c  = act ? cosf(ph) : 0.0f;
        float sn = act ? sinf(ph) : 0.0f;
        float sc = c, ss = sn;
        #pragma unroll
        for (int off = 16; off; off >>= 1) {
            sc += __shfl_down_sync(0xFFFFFFFFu, sc, off);
            ss += __shfl_down_sync(0xFFFFFFFFu, ss, off);
        }
        sc = __shfl_sync(0xFFFFFFFFu, sc, 0);
        ss = __shfl_sync(0xFFFFFFFFu, ss, 0);
        float mc = sc / 28.0f, ms = ss / 28.0f;
        float coup = ms * c - mc * sn;
        ph = mod2pi(ph + 0.01f * (omega + am * coup));
    }
    if (act) {
        float c = cosf(ph), sn = sinf(ph);
        __nv_bfloat16 chi, clo, shi, slo;
        bf16split(c, chi, clo); bf16split(sn, shi, slo);
        __nv_bfloat16* ar = g_Abf + (size_t)gw * KGEMM;
        ar[lane] = chi;       ar[28 + lane] = shi;
        ar[56 + lane] = chi;  ar[84 + lane] = shi;
        ar[112 + lane] = clo; ar[140 + lane] = slo;
    }
}

// ---------------------------------------------------------------------------
// HMMA GEMM (R8, correctness-proven): 128x128 tile/CTA, 512 threads / 16
// warps (4x4), warp = 32x32. SMEM rows 368 B. Fused rowbest epilogue.
// ---------------------------------------------------------------------------
#define GT_ROWB   368
#define GT_TILE   (128 * GT_ROWB)           // 47104
#define GT_SMEM_TOTAL (2 * GT_TILE)         // 94208

__global__ __launch_bounds__(512, 1)
void gemm_kernel(float* __restrict__ sim) {
    extern __shared__ char smg[];
    const int tid = threadIdx.x;
    const int lane = tid & 31;
    const int w = tid >> 5;
    const int warpRow = w >> 2;       // 0..3  (32 rows each)
    const int warpCol = w & 3;        // 0..3  (32 cols each)
    uint32_t smA = smem_u32(smg);
    uint32_t smB = smA + GT_TILE;

    // ---- stage tiles: 22 chunks of 16B per row (K<176) ----
    {
        const uint4* srcA = (const uint4*)(g_Abf + (size_t)blockIdx.y * 128 * KGEMM);
        const uint4* srcB = (const uint4*)(g_Bbf + (size_t)blockIdx.x * 128 * KGEMM);
        #pragma unroll
        for (int i = 0; i < 11; ++i) {
            int idx = tid + i * 512;          // 0..5631 over both tiles
            int half = idx >= 2816;
            int e = half ? idx - 2816 : idx;  // 0..2815
            int r = e / 22, q = e - r * 22;
            int off = r * GT_ROWB + q * 16;
            if (half) *(uint4*)(smg + GT_TILE + off) = srcB[r * 24 + q];
            else      *(uint4*)(smg + off) = srcA[r * 24 + q];
        }
    }
    __syncthreads();

    float acc[2][4][4];
    #pragma unroll
    for (int mt = 0; mt < 2; ++mt)
        #pragma unroll
        for (int nt = 0; nt < 4; ++nt)
            #pragma unroll
            for (int e = 0; e < 4; ++e) acc[mt][nt][e] = 0.0f;

    const uint32_t aBase = smA + (warpRow * 32 + (lane & 15)) * GT_ROWB + (lane >> 4) * 16;
    const uint32_t bBase = smB + (warpCol * 32 + (lane & 7)) * GT_ROWB + ((lane >> 3) & 1) * 16;

    #pragma unroll
    for (int kt = 0; kt < KTILES; ++kt) {
        uint32_t af[2][4], bf[4][2];
        #pragma unroll
        for (int mt = 0; mt < 2; ++mt)
            ldm_x4(af[mt], aBase + mt * 16 * GT_ROWB + kt * 32);
        #pragma unroll
        for (int nt = 0; nt < 4; ++nt)
            ldm_x2(bf[nt], bBase + nt * 8 * GT_ROWB + kt * 32);
        #pragma unroll
        for (int mt = 0; mt < 2; ++mt)
            #pragma unroll
            for (int nt = 0; nt < 4; ++nt)
                mma16816(acc[mt][nt], af[mt], bf[nt]);
    }

    // ---- epilogue: scale, store, fused rowbest ----
    const float invden = 1.0f / DENOM_F;
    const int g = lane >> 2, tq = lane & 3;
    const int rowg = blockIdx.y * 128 + warpRow * 32 + g;
    const int colg = blockIdx.x * 128 + warpCol * 32 + tq * 2;

    #pragma unroll
    for (int mt = 0; mt < 2; ++mt) {
        int r0 = rowg + mt * 16;
        int r1 = r0 + 8;
        unsigned long long best0 = 0ull, best1 = 0ull;
        #pragma unroll
        for (int nt = 0; nt < 4; ++nt) {
            int col = colg + nt * 8;
            float2 v0, v1;
            v0.x = acc[mt][nt][0] * invden; v0.y = acc[mt][nt][1] * invden;
            v1.x = acc[mt][nt][2] * invden; v1.y = acc[mt][nt][3] * invden;
            *(float2*)(sim + (size_t)r0 * N_DET + col) = v0;
            *(float2*)(sim + (size_t)r1 * N_DET + col) = v1;
            unsigned long long k;
            k = ((unsigned long long)ordf(v0.x) << 32) | (unsigned)(~(unsigned)col);
            if (k > best0) best0 = k;
            k = ((unsigned long long)ordf(v0.y) << 32) | (unsigned)(~(unsigned)(col + 1));
            if (k > best0) best0 = k;
            k = ((unsigned long long)ordf(v1.x) << 32) | (unsigned)(~(unsigned)col);
            if (k > best1) best1 = k;
            k = ((unsigned long long)ordf(v1.y) << 32) | (unsigned)(~(unsigned)(col + 1));
            if (k > best1) best1 = k;
        }
        #pragma unroll
        for (int off = 1; off < 4; off <<= 1) {
            unsigned long long o0 = __shfl_xor_sync(0xFFFFFFFFu, best0, off);
            unsigned long long o1 = __shfl_xor_sync(0xFFFFFFFFu, best1, off);
            if (o0 > best0) best0 = o0;
            if (o1 > best1) best1 = o1;
        }
        if (tq == 0) {
            atomicMax(&g_rowbest[r0], best0);
            atomicMax(&g_rowbest[r1], best1);
        }
    }
}

// ---------------------------------------------------------------------------
// Parallel greedy match (exact equivalent of the sequential scan).
// ---------------------------------------------------------------------------
__global__ void claim_kernel() {
    int i = blockIdx.x * blockDim.x + threadIdx.x;
    if (i >= N_DET) return;
    const unsigned ORD_THR = __float_as_uint(0.3f) | 0x80000000u;
    unsigned long long rb = g_rowbest[i];
    unsigned ordsim = (unsigned)(rb >> 32);
    if (ordsim > ORD_THR) {
        unsigned j = ~(unsigned)rb;
        unsigned long long claimkey = (rb & 0xFFFFFFFF00000000ull) | (unsigned)(~(unsigned)i);
        atomicMax(&g_colbest[j], claimkey);
    }
}

__global__ void resolve_kernel(float* __restrict__ matches) {
    int i = blockIdx.x * blockDim.x + threadIdx.x;
    if (i >= N_DET) return;
    const unsigned ORD_THR = __float_as_uint(0.3f) | 0x80000000u;
    unsigned long long rb = g_rowbest[i];
    unsigned ordsim = (unsigned)(rb >> 32);
    float m = -1.0f;
    if (ordsim > ORD_THR) {
        unsigned j = ~(unsigned)rb;
        unsigned long long claimkey = (rb & 0xFFFFFFFF00000000ull) | (unsigned)(~(unsigned)i);
        if (g_colbest[j] == claimkey) m = (float)j;
    }
    matches[i] = m;
}

// ---------------------------------------------------------------------------
extern "C" void kernel_launch(void* const* d_in, const int* in_sizes, int n_in,
                              void* d_out, int out_size) {
    const float* det_t  = (const float*)d_in[0];
    const float* det_t1 = (const float*)d_in[1];
    const float* Wp1 = (const float*)d_in[2];
    const float* bp1 = (const float*)d_in[3];
    const float* Wp2 = (const float*)d_in[4];
    const float* bp2 = (const float*)d_in[5];
    const float* Wa1 = (const float*)d_in[6];
    const float* ba1 = (const float*)d_in[7];
    const float* Wa2 = (const float*)d_in[8];
    const float* ba2 = (const float*)d_in[9];
    float* out = (float*)d_out;                 // [0,4096): matches, then sim

    cudaFuncSetAttribute(encode_kernel, cudaFuncAttributeMaxDynamicSharedMemorySize,
                         ENC_SMEM_FLOATS * 4);
    cudaFuncSetAttribute(gemm_kernel, cudaFuncAttributeMaxDynamicSharedMemorySize,
                         GT_SMEM_TOTAL);

    init_kernel<<<16, 256>>>();
    encode_kernel<<<256, 256, ENC_SMEM_FLOATS * 4>>>(det_t, det_t1,
                                                     Wp1, bp1, Wp2, bp2,
                                                     Wa1, ba1, Wa2, ba2);
    evolve_kernel<<<512, 256>>>();
    gemm_kernel<<<dim3(32, 32), 512, GT_SMEM_TOTAL>>>(out + N_DET);
    claim_kernel<<<16, 256>>>();
    resolve_kernel<<<16, 256>>>(out);
}

// round 10
// speedup vs baseline: 1.2520x; 1.0295x over previous
#include <cuda_runtime.h>
#include <cuda_bf16.h>
#include <cstdint>

// ---------------------------------------------------------------------------
// PhaseTracker: encode -> evolve -> HMMA bf16-split GEMM (64x64 warps) -> greedy
// ---------------------------------------------------------------------------

#define N_DET   4096
#define DIM     128
#define HID     64
#define NOSC    28
#define KGEMM   192          // 3 blocks of 56 (hi|hi|lo vs hi|lo|hi) padded
#define KTILES  11           // k < 176 (data ends at 168, [168,176) zeroed)
#define TWO_PI_F 6.283185307179586f
#define INV_2PI  0.15915494309189535f
#define DENOM_F  28.000010583006244f   // (sqrt(28)+1e-6)^2

__device__ float g_phase[N_DET * NOSC];
__device__ float g_amp[N_DET * NOSC];
__device__ __align__(16) __nv_bfloat16 g_Abf[N_DET * KGEMM];  // [hi56|hi56|lo56|pad]
__device__ __align__(16) __nv_bfloat16 g_Bbf[N_DET * KGEMM];  // [hi56|lo56|hi56|pad]
__device__ unsigned long long g_rowbest[N_DET];
__device__ unsigned long long g_colbest[N_DET];

__device__ __forceinline__ float mod2pi(float v) {
    return v - floorf(v * INV_2PI) * TWO_PI_F;
}
__device__ __forceinline__ float softplusf(float x) {
    return fmaxf(x, 0.0f) + log1pf(expf(-fabsf(x)));
}
__device__ __forceinline__ unsigned ordf(float x) {
    unsigned u = __float_as_uint(x);
    return (u & 0x80000000u) ? ~u : (u | 0x80000000u);
}
__device__ __forceinline__ void bf16split(float v, __nv_bfloat16& hi, __nv_bfloat16& lo) {
    hi = __float2bfloat16_rn(v);
    lo = __float2bfloat16_rn(v - __bfloat162float(hi));
}
__device__ __forceinline__ uint32_t smem_u32(const void* p) {
    uint32_t a;
    asm("{ .reg .u64 t; cvta.to.shared.u64 t, %1; cvt.u32.u64 %0, t; }" : "=r"(a) : "l"(p));
    return a;
}
__device__ __forceinline__ void ldm_x4(uint32_t* r, uint32_t addr) {
    asm volatile("ldmatrix.sync.aligned.m8n8.x4.shared.b16 {%0,%1,%2,%3}, [%4];"
                 : "=r"(r[0]), "=r"(r[1]), "=r"(r[2]), "=r"(r[3]) : "r"(addr));
}
__device__ __forceinline__ void mma16816(float* c, const uint32_t* a, const uint32_t* b) {
    asm volatile("mma.sync.aligned.m16n8k16.row.col.f32.bf16.bf16.f32 "
                 "{%0,%1,%2,%3}, {%4,%5,%6,%7}, {%8,%9}, {%0,%1,%2,%3};"
                 : "+f"(c[0]), "+f"(c[1]), "+f"(c[2]), "+f"(c[3])
                 : "r"(a[0]), "r"(a[1]), "r"(a[2]), "r"(a[3]), "r"(b[0]), "r"(b[1]));
}

// ---------------------------------------------------------------------------
__global__ void init_kernel() {
    int i = blockIdx.x * blockDim.x + threadIdx.x;
    if (i < N_DET) {
        g_rowbest[i] = 0ull; g_colbest[i] = 0ull;
        uint4 z = make_uint4(0, 0, 0, 0);
        uint4* pa = (uint4*)((char*)g_Abf + (size_t)i * 384 + 336);
        uint4* pb = (uint4*)((char*)g_Bbf + (size_t)i * 384 + 336);
        pa[0] = z; pa[1] = z; pa[2] = z;
        pb[0] = z; pb[1] = z; pb[2] = z;
    }
}

// ---------------------------------------------------------------------------
// Encode (R7-proven): two rows per weight read.
// ---------------------------------------------------------------------------
#define ENC_W1STR 132
#define ENC_W2STR 68
#define ENC_SMEM_FLOATS (2*HID*ENC_W1STR + 2*NOSC*ENC_W2STR + 512 + 512)

__global__ __launch_bounds__(256, 2)
void encode_kernel(const float* __restrict__ det_t, const float* __restrict__ det_t1,
                   const float* __restrict__ Wp1, const float* __restrict__ bp1,
                   const float* __restrict__ Wp2, const float* __restrict__ bp2,
                   const float* __restrict__ Wa1, const float* __restrict__ ba1,
                   const float* __restrict__ Wa2, const float* __restrict__ ba2) {
    extern __shared__ float sm[];
    float* wp1T = sm;
    float* wa1T = wp1T + HID * ENC_W1STR;
    float* wp2T = wa1T + HID * ENC_W1STR;
    float* wa2T = wp2T + NOSC * ENC_W2STR;
    float* xs   = wa2T + NOSC * ENC_W2STR;     // 4 x 128
    float* hs   = xs + 512;                    // 4 x 128

    int tid = threadIdx.x;
    for (int idx = tid; idx < DIM * HID; idx += 256) {
        int k = idx >> 6, j = idx & 63;
        wp1T[j * ENC_W1STR + k] = Wp1[idx];
        wa1T[j * ENC_W1STR + k] = Wa1[idx];
    }
    for (int idx = tid; idx < HID * NOSC; idx += 256) {
        int k = idx / NOSC, j = idx % NOSC;
        wp2T[j * ENC_W2STR + k] = Wp2[idx];
        wa2T[j * ENC_W2STR + k] = Wa2[idx];
    }

    const int quad = tid >> 7;
    const int t    = tid & 127;
    const int r0 = 2 * quad, r1 = r0 + 1;

    for (int it = 0; it < 8; ++it) {
        int rowbase = blockIdx.x * 32 + it * 4;
        bool isT = rowbase < N_DET;
        const float* X = isT ? (det_t + (size_t)rowbase * DIM)
                             : (det_t1 + (size_t)(rowbase - N_DET) * DIM);
        __syncthreads();
        if (tid < 128) {
            ((float4*)xs)[tid] = ((const float4*)X)[tid];
        }
        __syncthreads();

        {
            bool doAmp = (t >= 64);
            if (!doAmp || isT) {
                int j = doAmp ? (t - 64) : t;
                const float4* w4 = (const float4*)(doAmp ? &wa1T[j * ENC_W1STR]
                                                         : &wp1T[j * ENC_W1STR]);
                const float4* x0 = (const float4*)(xs + r0 * 128);
                const float4* x1 = (const float4*)(xs + r1 * 128);
                float b = doAmp ? ba1[j] : bp1[j];
                float a0 = b, a1 = b, c0 = 0.0f, c1 = 0.0f;
                #pragma unroll
                for (int k4 = 0; k4 < 32; k4 += 2) {
                    float4 w = w4[k4];
                    float4 xa = x0[k4], xb = x1[k4];
                    a0 += w.x * xa.x + w.y * xa.y + w.z * xa.z + w.w * xa.w;
                    a1 += w.x * xb.x + w.y * xb.y + w.z * xb.z + w.w * xb.w;
                    float4 w2 = w4[k4 + 1];
                    float4 xc = x0[k4 + 1], xd = x1[k4 + 1];
                    c0 += w2.x * xc.x + w2.y * xc.y + w2.z * xc.z + w2.w * xc.w;
                    c1 += w2.x * xd.x + w2.y * xd.y + w2.z * xd.z + w2.w * xd.w;
                }
                hs[r0 * 128 + t] = fmaxf(a0 + c0, 0.0f);
                hs[r1 * 128 + t] = fmaxf(a1 + c1, 0.0f);
            }
        }
        __syncthreads();

        int lane = t & 31, wgrp = t >> 5;
        if (wgrp == 0 && lane < NOSC) {               // phase head
            const float4* w4 = (const float4*)&wp2T[lane * ENC_W2STR];
            const float4* h0 = (const float4*)(hs + r0 * 128);
            const float4* h1 = (const float4*)(hs + r1 * 128);
            float b = bp2[lane];
            float p0 = b, p1 = b, q0 = 0.0f, q1 = 0.0f;
            #pragma unroll
            for (int k4 = 0; k4 < 16; k4 += 2) {
                float4 w = w4[k4];
                float4 ha = h0[k4], hb = h1[k4];
                p0 += w.x * ha.x + w.y * ha.y + w.z * ha.z + w.w * ha.w;
                p1 += w.x * hb.x + w.y * hb.y + w.z * hb.z + w.w * hb.w;
                float4 w2 = w4[k4 + 1];
                float4 hc = h0[k4 + 1], hd = h1[k4 + 1];
                q0 += w2.x * hc.x + w2.y * hc.y + w2.z * hc.z + w2.w * hc.w;
                q1 += w2.x * hd.x + w2.y * hd.y + w2.z * hd.z + w2.w * hd.w;
            }
            float ph0 = mod2pi(p0 + q0), ph1 = mod2pi(p1 + q1);
            int gr0 = rowbase + r0, gr1 = rowbase + r1;
            if (isT) {
                g_phase[gr0 * NOSC + lane] = ph0;
                g_phase[gr1 * NOSC + lane] = ph1;
            } else {
                // B' row layout: [cos_hi28 sin_hi28 | cos_lo28 sin_lo28 | cos_hi28 sin_hi28]
                int cc0 = gr0 - N_DET, cc1 = gr1 - N_DET;
                float cv0 = cosf(ph0), sv0 = sinf(ph0);
                float cv1 = cosf(ph1), sv1 = sinf(ph1);
                __nv_bfloat16 chi, clo, shi, slo;
                __nv_bfloat16* br;
                br = g_Bbf + (size_t)cc0 * KGEMM;
                bf16split(cv0, chi, clo); bf16split(sv0, shi, slo);
                br[lane] = chi;       br[28 + lane] = shi;
                br[56 + lane] = clo;  br[84 + lane] = slo;
                br[112 + lane] = chi; br[140 + lane] = shi;
                br = g_Bbf + (size_t)cc1 * KGEMM;
                bf16split(cv1, chi, clo); bf16split(sv1, shi, slo);
                br[lane] = chi;       br[28 + lane] = shi;
                br[56 + lane] = clo;  br[84 + lane] = slo;
                br[112 + lane] = chi; br[140 + lane] = shi;
            }
        } else if (wgrp == 1 && lane < NOSC && isT) { // amp head
            const float4* w4 = (const float4*)&wa2T[lane * ENC_W2STR];
            const float4* h0 = (const float4*)(hs + r0 * 128 + 64);
            const float4* h1 = (const float4*)(hs + r1 * 128 + 64);
            float b = ba2[lane];
            float p0 = b, p1 = b, q0 = 0.0f, q1 = 0.0f;
            #pragma unroll
            for (int k4 = 0; k4 < 16; k4 += 2) {
                float4 w = w4[k4];
                float4 ha = h0[k4], hb = h1[k4];
                p0 += w.x * ha.x + w.y * ha.y + w.z * ha.z + w.w * ha.w;
                p1 += w.x * hb.x + w.y * hb.y + w.z * hb.z + w.w * hb.w;
                float4 w2 = w4[k4 + 1];
                float4 hc = h0[k4 + 1], hd = h1[k4 + 1];
                q0 += w2.x * hc.x + w2.y * hc.y + w2.z * hc.z + w2.w * hc.w;
                q1 += w2.x * hd.x + w2.y * hd.y + w2.z * hd.z + w2.w * hd.w;
            }
            g_amp[(rowbase + r0) * NOSC + lane] = softplusf(p0 + q0);
            g_amp[(rowbase + r1) * NOSC + lane] = softplusf(p1 + q1);
        }
    }
}

// ---------------------------------------------------------------------------
// Evolve (R7-proven): 5 Kuramoto steps, one warp per row.
// ---------------------------------------------------------------------------
__global__ void evolve_kernel() {
    int gw   = (blockIdx.x * blockDim.x + threadIdx.x) >> 5;
    int lane = threadIdx.x & 31;
    if (gw >= N_DET) return;
    bool act = lane < NOSC;

    float ph = act ? g_phase[gw * NOSC + lane] : 0.0f;
    float am = act ? g_amp[gw * NOSC + lane] : 0.0f;
    float omega = TWO_PI_F * (lane < 4 ? 2.0f : (lane < 12 ? 6.0f : 40.0f));

    #pragma unroll
    for (int s = 0; s < 5; ++s) {
        float c  = act ? cosf(ph) : 0.0f;
        float sn = act ? sinf(ph) : 0.0f;
        float sc = c, ss = sn;
        #pragma unroll
        for (int off = 16; off; off >>= 1) {
            sc += __shfl_down_sync(0xFFFFFFFFu, sc, off);
            ss += __shfl_down_sync(0xFFFFFFFFu, ss, off);
        }
        sc = __shfl_sync(0xFFFFFFFFu, sc, 0);
        ss = __shfl_sync(0xFFFFFFFFu, ss, 0);
        float mc = sc / 28.0f, ms = ss / 28.0f;
        float coup = ms * c - mc * sn;
        ph = mod2pi(ph + 0.01f * (omega + am * coup));
    }
    if (act) {
        float c = cosf(ph), sn = sinf(ph);
        __nv_bfloat16 chi, clo, shi, slo;
        bf16split(c, chi, clo); bf16split(sn, shi, slo);
        __nv_bfloat16* ar = g_Abf + (size_t)gw * KGEMM;
        ar[lane] = chi;       ar[28 + lane] = shi;
        ar[56 + lane] = chi;  ar[84 + lane] = shi;
        ar[112 + lane] = clo; ar[140 + lane] = slo;
    }
}

// ---------------------------------------------------------------------------
// HMMA GEMM: 128x256 tile/CTA, 256 threads / 8 warps (2x4), warp = 64x64.
// 1.0 LDS-wavefront per MMA (vs 1.5 in R7). SMEM rows 368 B. Fused rowbest.
// ---------------------------------------------------------------------------
#define GT_ROWB   368
#define GT_TILE_A (128 * GT_ROWB)           // 47104
#define GT_TILE_B (256 * GT_ROWB)           // 94208
#define GT_SMEM_TOTAL (GT_TILE_A + GT_TILE_B)  // 141312

__global__ __launch_bounds__(256, 1)
void gemm_kernel(float* __restrict__ sim) {
    extern __shared__ char smg[];
    const int tid = threadIdx.x;
    const int lane = tid & 31;
    const int w = tid >> 5;
    const int warpRow = w >> 2;       // 0..1  (64 rows each)
    const int warpCol = w & 3;        // 0..3  (64 cols each)
    uint32_t smA = smem_u32(smg);
    uint32_t smB = smA + GT_TILE_A;

    // ---- stage tiles: 22 chunks of 16B per row (K<176) ----
    {
        const uint4* srcA = (const uint4*)(g_Abf + (size_t)blockIdx.y * 128 * KGEMM);
        const uint4* srcB = (const uint4*)(g_Bbf + (size_t)blockIdx.x * 256 * KGEMM);
        // A: 128*22 = 2816 chunks, B: 256*22 = 5632 chunks, total 8448
        #pragma unroll
        for (int i = 0; i < 33; ++i) {
            int idx = tid + i * 256;          // 0..8447
            int half = idx >= 2816;
            int e = half ? idx - 2816 : idx;
            int r = e / 22, q = e - r * 22;
            int off = r * GT_ROWB + q * 16;
            if (half) *(uint4*)(smg + GT_TILE_A + off) = srcB[r * 24 + q];
            else      *(uint4*)(smg + off) = srcA[r * 24 + q];
        }
    }
    __syncthreads();

    float acc[4][8][4];
    #pragma unroll
    for (int mt = 0; mt < 4; ++mt)
        #pragma unroll
        for (int nt = 0; nt < 8; ++nt)
            #pragma unroll
            for (int e = 0; e < 4; ++e) acc[mt][nt][e] = 0.0f;

    // A fragment addresses (proven R7 math): m16k16 per ldm_x4
    const uint32_t aBase = smA + (warpRow * 64 + (lane & 15)) * GT_ROWB + (lane >> 4) * 16;
    // B fragment addresses: n16k16 per ldm_x4 -> two n8k16 fragments
    //   lanes 0-7:  n0-7  k0-7 | 8-15: n0-7 k8-15 | 16-23: n8-15 k0-7 | 24-31: n8-15 k8-15
    const uint32_t bBase = smB + (warpCol * 64 + (lane & 7) + (lane >> 4) * 8) * GT_ROWB
                               + ((lane >> 3) & 1) * 16;

    #pragma unroll 2
    for (int kt = 0; kt < KTILES; ++kt) {
        uint32_t af[4][4];
        uint32_t bq[4][4];                // bq[p] covers n-tiles 2p, 2p+1
        #pragma unroll
        for (int mt = 0; mt < 4; ++mt)
            ldm_x4(af[mt], aBase + mt * 16 * GT_ROWB + kt * 32);
        #pragma unroll
        for (int p = 0; p < 4; ++p)
            ldm_x4(bq[p], bBase + p * 16 * GT_ROWB + kt * 32);
        #pragma unroll
        for (int mt = 0; mt < 4; ++mt)
            #pragma unroll
            for (int p = 0; p < 4; ++p) {
                mma16816(acc[mt][2 * p],     af[mt], &bq[p][0]);   // {r0,r1}
                mma16816(acc[mt][2 * p + 1], af[mt], &bq[p][2]);   // {r2,r3}
            }
    }

    // ---- epilogue: scale, store, fused rowbest ----
    const float invden = 1.0f / DENOM_F;
    const int g = lane >> 2, tq = lane & 3;
    const int rowg = blockIdx.y * 128 + warpRow * 64 + g;
    const int colg = blockIdx.x * 256 + warpCol * 64 + tq * 2;

    #pragma unroll
    for (int mt = 0; mt < 4; ++mt) {
        int r0 = rowg + mt * 16;
        int r1 = r0 + 8;
        unsigned long long best0 = 0ull, best1 = 0ull;
        #pragma unroll
        for (int nt = 0; nt < 8; ++nt) {
            int col = colg + nt * 8;
            float2 v0, v1;
            v0.x = acc[mt][nt][0] * invden; v0.y = acc[mt][nt][1] * invden;
            v1.x = acc[mt][nt][2] * invden; v1.y = acc[mt][nt][3] * invden;
            *(float2*)(sim + (size_t)r0 * N_DET + col) = v0;
            *(float2*)(sim + (size_t)r1 * N_DET + col) = v1;
            unsigned long long k;
            k = ((unsigned long long)ordf(v0.x) << 32) | (unsigned)(~(unsigned)col);
            if (k > best0) best0 = k;
            k = ((unsigned long long)ordf(v0.y) << 32) | (unsigned)(~(unsigned)(col + 1));
            if (k > best0) best0 = k;
            k = ((unsigned long long)ordf(v1.x) << 32) | (unsigned)(~(unsigned)col);
            if (k > best1) best1 = k;
            k = ((unsigned long long)ordf(v1.y) << 32) | (unsigned)(~(unsigned)(col + 1));
            if (k > best1) best1 = k;
        }
        #pragma unroll
        for (int off = 1; off < 4; off <<= 1) {
            unsigned long long o0 = __shfl_xor_sync(0xFFFFFFFFu, best0, off);
            unsigned long long o1 = __shfl_xor_sync(0xFFFFFFFFu, best1, off);
            if (o0 > best0) best0 = o0;
            if (o1 > best1) best1 = o1;
        }
        if (tq == 0) {
            atomicMax(&g_rowbest[r0], best0);
            atomicMax(&g_rowbest[r1], best1);
        }
    }
}

// ---------------------------------------------------------------------------
// Parallel greedy match (exact equivalent of the sequential scan).
// ---------------------------------------------------------------------------
__global__ void claim_kernel() {
    int i = blockIdx.x * blockDim.x + threadIdx.x;
    if (i >= N_DET) return;
    const unsigned ORD_THR = __float_as_uint(0.3f) | 0x80000000u;
    unsigned long long rb = g_rowbest[i];
    unsigned ordsim = (unsigned)(rb >> 32);
    if (ordsim > ORD_THR) {
        unsigned j = ~(unsigned)rb;
        unsigned long long claimkey = (rb & 0xFFFFFFFF00000000ull) | (unsigned)(~(unsigned)i);
        atomicMax(&g_colbest[j], claimkey);
    }
}

__global__ void resolve_kernel(float* __restrict__ matches) {
    int i = blockIdx.x * blockDim.x + threadIdx.x;
    if (i >= N_DET) return;
    const unsigned ORD_THR = __float_as_uint(0.3f) | 0x80000000u;
    unsigned long long rb = g_rowbest[i];
    unsigned ordsim = (unsigned)(rb >> 32);
    float m = -1.0f;
    if (ordsim > ORD_THR) {
        unsigned j = ~(unsigned)rb;
        unsigned long long claimkey = (rb & 0xFFFFFFFF00000000ull) | (unsigned)(~(unsigned)i);
        if (g_colbest[j] == claimkey) m = (float)j;
    }
    matches[i] = m;
}

// ---------------------------------------------------------------------------
extern "C" void kernel_launch(void* const* d_in, const int* in_sizes, int n_in,
                              void* d_out, int out_size) {
    const float* det_t  = (const float*)d_in[0];
    const float* det_t1 = (const float*)d_in[1];
    const float* Wp1 = (const float*)d_in[2];
    const float* bp1 = (const float*)d_in[3];
    const float* Wp2 = (const float*)d_in[4];
    const float* bp2 = (const float*)d_in[5];
    const float* Wa1 = (const float*)d_in[6];
    const float* ba1 = (const float*)d_in[7];
    const float* Wa2 = (const float*)d_in[8];
    const float* ba2 = (const float*)d_in[9];
    float* out = (float*)d_out;                 // [0,4096): matches, then sim

    cudaFuncSetAttribute(encode_kernel, cudaFuncAttributeMaxDynamicSharedMemorySize,
                         ENC_SMEM_FLOATS * 4);
    cudaFuncSetAttribute(gemm_kernel, cudaFuncAttributeMaxDynamicSharedMemorySize,
                         GT_SMEM_TOTAL);

    init_kernel<<<16, 256>>>();
    encode_kernel<<<256, 256, ENC_SMEM_FLOATS * 4>>>(det_t, det_t1,
                                                     Wp1, bp1, Wp2, bp2,
                                                     Wa1, ba1, Wa2, ba2);
    evolve_kernel<<<512, 256>>>();
    gemm_kernel<<<dim3(16, 32), 256, GT_SMEM_TOTAL>>>(out + N_DET);
    claim_kernel<<<16, 256>>>();
    resolve_kernel<<<16, 256>>>(out);
}

// round 12
// speedup vs baseline: 1.3580x; 1.0847x over previous
#include <cuda_runtime.h>
#include <cuda_bf16.h>
#include <cstdint>

// ---------------------------------------------------------------------------
// PhaseTracker: encode -> evolve -> HMMA bf16-split GEMM (2 CTA/SM) -> greedy
// ---------------------------------------------------------------------------

#define N_DET   4096
#define DIM     128
#define HID     64
#define NOSC    28
#define KGEMM   192          // 3 blocks of 56 (hi|hi|lo vs hi|lo|hi) padded
#define KTILES  11           // k < 176 (data ends at 168, [168,176) zeroed)
#define TWO_PI_F 6.283185307179586f
#define INV_2PI  0.15915494309189535f
#define DENOM_F  28.000010583006244f   // (sqrt(28)+1e-6)^2

__device__ float g_phase[N_DET * NOSC];
__device__ float g_amp[N_DET * NOSC];
__device__ __align__(16) __nv_bfloat16 g_Abf[N_DET * KGEMM];  // [hi56|hi56|lo56|pad]
__device__ __align__(16) __nv_bfloat16 g_Bbf[N_DET * KGEMM];  // [hi56|lo56|hi56|pad]
__device__ unsigned long long g_rowbest[N_DET];
__device__ unsigned long long g_colbest[N_DET];

__device__ __forceinline__ float mod2pi(float v) {
    return v - floorf(v * INV_2PI) * TWO_PI_F;
}
__device__ __forceinline__ float softplusf(float x) {
    return fmaxf(x, 0.0f) + log1pf(expf(-fabsf(x)));
}
__device__ __forceinline__ unsigned ordf(float x) {
    unsigned u = __float_as_uint(x);
    return (u & 0x80000000u) ? ~u : (u | 0x80000000u);
}
__device__ __forceinline__ void bf16split(float v, __nv_bfloat16& hi, __nv_bfloat16& lo) {
    hi = __float2bfloat16_rn(v);
    lo = __float2bfloat16_rn(v - __bfloat162float(hi));
}
__device__ __forceinline__ uint32_t smem_u32(const void* p) {
    uint32_t a;
    asm("{ .reg .u64 t; cvta.to.shared.u64 t, %1; cvt.u32.u64 %0, t; }" : "=r"(a) : "l"(p));
    return a;
}
__device__ __forceinline__ void ldm_x4(uint32_t* r, uint32_t addr) {
    asm volatile("ldmatrix.sync.aligned.m8n8.x4.shared.b16 {%0,%1,%2,%3}, [%4];"
                 : "=r"(r[0]), "=r"(r[1]), "=r"(r[2]), "=r"(r[3]) : "r"(addr));
}
__device__ __forceinline__ void mma16816(float* c, const uint32_t* a, const uint32_t* b) {
    asm volatile("mma.sync.aligned.m16n8k16.row.col.f32.bf16.bf16.f32 "
                 "{%0,%1,%2,%3}, {%4,%5,%6,%7}, {%8,%9}, {%0,%1,%2,%3};"
                 : "+f"(c[0]), "+f"(c[1]), "+f"(c[2]), "+f"(c[3])
                 : "r"(a[0]), "r"(a[1]), "r"(a[2]), "r"(a[3]), "r"(b[0]), "r"(b[1]));
}

// ---------------------------------------------------------------------------
__global__ void init_kernel() {
    int i = blockIdx.x * blockDim.x + threadIdx.x;
    if (i < N_DET) {
        g_rowbest[i] = 0ull; g_colbest[i] = 0ull;
        uint4 z = make_uint4(0, 0, 0, 0);
        uint4* pa = (uint4*)((char*)g_Abf + (size_t)i * 384 + 336);
        uint4* pb = (uint4*)((char*)g_Bbf + (size_t)i * 384 + 336);
        pa[0] = z; pa[1] = z; pa[2] = z;
        pb[0] = z; pb[1] = z; pb[2] = z;
    }
}

// ---------------------------------------------------------------------------
// Encode: FOUR rows per thread per weight read. 128 blocks x 256 threads,
// 8 iterations of 8 rows.
// ---------------------------------------------------------------------------
#define ENC_W1STR 132
#define ENC_W2STR 68
#define ENC_SMEM_FLOATS (2*HID*ENC_W1STR + 2*NOSC*ENC_W2STR + 1024 + 1024)

__global__ __launch_bounds__(256, 2)
void encode_kernel(const float* __restrict__ det_t, const float* __restrict__ det_t1,
                   const float* __restrict__ Wp1, const float* __restrict__ bp1,
                   const float* __restrict__ Wp2, const float* __restrict__ bp2,
                   const float* __restrict__ Wa1, const float* __restrict__ ba1,
                   const float* __restrict__ Wa2, const float* __restrict__ ba2) {
    extern __shared__ float sm[];
    float* wp1T = sm;
    float* wa1T = wp1T + HID * ENC_W1STR;
    float* wp2T = wa1T + HID * ENC_W1STR;
    float* wa2T = wp2T + NOSC * ENC_W2STR;
    float* xs   = wa2T + NOSC * ENC_W2STR;     // 8 x 128
    float* hs   = xs + 1024;                   // 8 x 128

    int tid = threadIdx.x;
    for (int idx = tid; idx < DIM * HID; idx += 256) {
        int k = idx >> 6, j = idx & 63;
        wp1T[j * ENC_W1STR + k] = Wp1[idx];
        wa1T[j * ENC_W1STR + k] = Wa1[idx];
    }
    for (int idx = tid; idx < HID * NOSC; idx += 256) {
        int k = idx / NOSC, j = idx % NOSC;
        wp2T[j * ENC_W2STR + k] = Wp2[idx];
        wa2T[j * ENC_W2STR + k] = Wa2[idx];
    }

    const int quad = tid >> 7;
    const int t    = tid & 127;
    const int rb0  = 4 * quad;                 // local rows rb0..rb0+3

    for (int it = 0; it < 8; ++it) {
        int rowbase = blockIdx.x * 64 + it * 8;
        bool isT = rowbase < N_DET;
        const float* X = isT ? (det_t + (size_t)rowbase * DIM)
                             : (det_t1 + (size_t)(rowbase - N_DET) * DIM);
        __syncthreads();
        ((float4*)xs)[tid] = ((const float4*)X)[tid];   // 8 rows x 128 floats
        __syncthreads();

        // ---- layer 1: 4 rows per thread ----
        {
            bool doAmp = (t >= 64);
            if (!doAmp || isT) {
                int j = doAmp ? (t - 64) : t;
                const float4* w4 = (const float4*)(doAmp ? &wa1T[j * ENC_W1STR]
                                                         : &wp1T[j * ENC_W1STR]);
                const float4* x0 = (const float4*)(xs + (rb0 + 0) * 128);
                const float4* x1 = (const float4*)(xs + (rb0 + 1) * 128);
                const float4* x2 = (const float4*)(xs + (rb0 + 2) * 128);
                const float4* x3 = (const float4*)(xs + (rb0 + 3) * 128);
                float b = doAmp ? ba1[j] : bp1[j];
                float a0 = b, a1 = b, a2 = b, a3 = b;
                #pragma unroll
                for (int k4 = 0; k4 < 32; ++k4) {
                    float4 w = w4[k4];
                    float4 v0 = x0[k4], v1 = x1[k4], v2 = x2[k4], v3 = x3[k4];
                    a0 += w.x * v0.x + w.y * v0.y + w.z * v0.z + w.w * v0.w;
                    a1 += w.x * v1.x + w.y * v1.y + w.z * v1.z + w.w * v1.w;
                    a2 += w.x * v2.x + w.y * v2.y + w.z * v2.z + w.w * v2.w;
                    a3 += w.x * v3.x + w.y * v3.y + w.z * v3.z + w.w * v3.w;
                }
                hs[(rb0 + 0) * 128 + t] = fmaxf(a0, 0.0f);
                hs[(rb0 + 1) * 128 + t] = fmaxf(a1, 0.0f);
                hs[(rb0 + 2) * 128 + t] = fmaxf(a2, 0.0f);
                hs[(rb0 + 3) * 128 + t] = fmaxf(a3, 0.0f);
            }
        }
        __syncthreads();

        // ---- layer 2: 4 rows per thread ----
        int lane = t & 31, wgrp = t >> 5;
        if (wgrp == 0 && lane < NOSC) {               // phase head
            const float4* w4 = (const float4*)&wp2T[lane * ENC_W2STR];
            const float4* h0 = (const float4*)(hs + (rb0 + 0) * 128);
            const float4* h1 = (const float4*)(hs + (rb0 + 1) * 128);
            const float4* h2 = (const float4*)(hs + (rb0 + 2) * 128);
            const float4* h3 = (const float4*)(hs + (rb0 + 3) * 128);
            float b = bp2[lane];
            float p0 = b, p1 = b, p2 = b, p3 = b;
            #pragma unroll
            for (int k4 = 0; k4 < 16; ++k4) {
                float4 w = w4[k4];
                float4 va = h0[k4], vb = h1[k4], vc = h2[k4], vd = h3[k4];
                p0 += w.x * va.x + w.y * va.y + w.z * va.z + w.w * va.w;
                p1 += w.x * vb.x + w.y * vb.y + w.z * vb.z + w.w * vb.w;
                p2 += w.x * vc.x + w.y * vc.y + w.z * vc.z + w.w * vc.w;
                p3 += w.x * vd.x + w.y * vd.y + w.z * vd.z + w.w * vd.w;
            }
            float ph[4] = { mod2pi(p0), mod2pi(p1), mod2pi(p2), mod2pi(p3) };
            if (isT) {
                #pragma unroll
                for (int r = 0; r < 4; ++r)
                    g_phase[(rowbase + rb0 + r) * NOSC + lane] = ph[r];
            } else {
                // B' row layout: [cos_hi28 sin_hi28 | cos_lo28 sin_lo28 | cos_hi28 sin_hi28]
                #pragma unroll
                for (int r = 0; r < 4; ++r) {
                    int cc = rowbase - N_DET + rb0 + r;
                    float cv = cosf(ph[r]), sv = sinf(ph[r]);
                    __nv_bfloat16 chi, clo, shi, slo;
                    bf16split(cv, chi, clo); bf16split(sv, shi, slo);
                    __nv_bfloat16* br = g_Bbf + (size_t)cc * KGEMM;
                    br[lane] = chi;       br[28 + lane] = shi;
                    br[56 + lane] = clo;  br[84 + lane] = slo;
                    br[112 + lane] = chi; br[140 + lane] = shi;
                }
            }
        } else if (wgrp == 1 && lane < NOSC && isT) { // amp head
            const float4* w4 = (const float4*)&wa2T[lane * ENC_W2STR];
            const float4* h0 = (const float4*)(hs + (rb0 + 0) * 128 + 64);   // FIXED: +64 floats
            const float4* h1 = (const float4*)(hs + (rb0 + 1) * 128 + 64);
            const float4* h2 = (const float4*)(hs + (rb0 + 2) * 128 + 64);
            const float4* h3 = (const float4*)(hs + (rb0 + 3) * 128 + 64);
            float b = ba2[lane];
            float p0 = b, p1 = b, p2 = b, p3 = b;
            #pragma unroll
            for (int k4 = 0; k4 < 16; ++k4) {
                float4 w = w4[k4];
                float4 va = h0[k4], vb = h1[k4], vc = h2[k4], vd = h3[k4];
                p0 += w.x * va.x + w.y * va.y + w.z * va.z + w.w * va.w;
                p1 += w.x * vb.x + w.y * vb.y + w.z * vb.z + w.w * vb.w;
                p2 += w.x * vc.x + w.y * vc.y + w.z * vc.z + w.w * vc.w;
                p3 += w.x * vd.x + w.y * vd.y + w.z * vd.z + w.w * vd.w;
            }
            g_amp[(rowbase + rb0 + 0) * NOSC + lane] = softplusf(p0);
            g_amp[(rowbase + rb0 + 1) * NOSC + lane] = softplusf(p1);
            g_amp[(rowbase + rb0 + 2) * NOSC + lane] = softplusf(p2);
            g_amp[(rowbase + rb0 + 3) * NOSC + lane] = softplusf(p3);
        }
    }
}

// ---------------------------------------------------------------------------
// Evolve (R7-proven): 5 Kuramoto steps, one warp per row.
// ---------------------------------------------------------------------------
__global__ void evolve_kernel() {
    int gw   = (blockIdx.x * blockDim.x + threadIdx.x) >> 5;
    int lane = threadIdx.x & 31;
    if (gw >= N_DET) return;
    bool act = lane < NOSC;

    float ph = act ? g_phase[gw * NOSC + lane] : 0.0f;
    float am = act ? g_amp[gw * NOSC + lane] : 0.0f;
    float omega = TWO_PI_F * (lane < 4 ? 2.0f : (lane < 12 ? 6.0f : 40.0f));

    #pragma unroll
    for (int s = 0; s < 5; ++s) {
        float c  = act ? cosf(ph) : 0.0f;
        float sn = act ? sinf(ph) : 0.0f;
        float sc = c, ss = sn;
        #pragma unroll
        for (int off = 16; off; off >>= 1) {
            sc += __shfl_down_sync(0xFFFFFFFFu, sc, off);
            ss += __shfl_down_sync(0xFFFFFFFFu, ss, off);
        }
        sc = __shfl_sync(0xFFFFFFFFu, sc, 0);
        ss = __shfl_sync(0xFFFFFFFFu, ss, 0);
        float mc = sc / 28.0f, ms = ss / 28.0f;
        float coup = ms * c - mc * sn;
        ph = mod2pi(ph + 0.01f * (omega + am * coup));
    }
    if (act) {
        float c = cosf(ph), sn = sinf(ph);
        __nv_bfloat16 chi, clo, shi, slo;
        bf16split(c, chi, clo); bf16split(sn, shi, slo);
        __nv_bfloat16* ar = g_Abf + (size_t)gw * KGEMM;
        ar[lane] = chi;       ar[28 + lane] = shi;
        ar[56 + lane] = chi;  ar[84 + lane] = shi;
        ar[112 + lane] = clo; ar[140 + lane] = slo;
    }
}

// ---------------------------------------------------------------------------
// HMMA GEMM: 128x128 tile/CTA, 256 threads / 8 warps (4x2), warp = 32x64.
// ~110 regs + 94KB smem -> 2 CTAs/SM. Fused rowbest epilogue.
// ---------------------------------------------------------------------------
#define GT_ROWB   368
#define GT_TILE   (128 * GT_ROWB)           // 47104
#define GT_SMEM_TOTAL (2 * GT_TILE)         // 94208

__global__ __launch_bounds__(256, 2)
void gemm_kernel(float* __restrict__ sim) {
    extern __shared__ char smg[];
    const int tid = threadIdx.x;
    const int lane = tid & 31;
    const int w = tid >> 5;
    const int warpRow = w & 3;        // 0..3  (32 rows each)
    const int warpCol = w >> 2;       // 0..1  (64 cols each)
    uint32_t smA = smem_u32(smg);
    uint32_t smB = smA + GT_TILE;

    // ---- stage tiles: 22 chunks of 16B per row (K<176) ----
    {
        const uint4* srcA = (const uint4*)(g_Abf + (size_t)blockIdx.y * 128 * KGEMM);
        const uint4* srcB = (const uint4*)(g_Bbf + (size_t)blockIdx.x * 128 * KGEMM);
        #pragma unroll
        for (int i = 0; i < 22; ++i) {
            int idx = tid + i * 256;          // 0..5631
            int half = idx >= 2816;
            int e = half ? idx - 2816 : idx;
            int r = e / 22, q = e - r * 22;
            int off = r * GT_ROWB + q * 16;
            if (half) *(uint4*)(smg + GT_TILE + off) = srcB[r * 24 + q];
            else      *(uint4*)(smg + off) = srcA[r * 24 + q];
        }
    }
    __syncthreads();

    float acc[2][8][4];
    #pragma unroll
    for (int mt = 0; mt < 2; ++mt)
        #pragma unroll
        for (int nt = 0; nt < 8; ++nt)
            #pragma unroll
            for (int e = 0; e < 4; ++e) acc[mt][nt][e] = 0.0f;

    // A fragments: m16k16 per ldm_x4
    const uint32_t aBase = smA + (warpRow * 32 + (lane & 15)) * GT_ROWB + (lane >> 4) * 16;
    // B fragments: n16k16 per ldm_x4 (proven R10 mapping)
    const uint32_t bBase = smB + (warpCol * 64 + (lane & 7) + (lane >> 4) * 8) * GT_ROWB
                               + ((lane >> 3) & 1) * 16;

    #pragma unroll 2
    for (int kt = 0; kt < KTILES; ++kt) {
        uint32_t af[2][4];
        uint32_t bq[4][4];                // bq[p] covers n-tiles 2p, 2p+1
        #pragma unroll
        for (int mt = 0; mt < 2; ++mt)
            ldm_x4(af[mt], aBase + mt * 16 * GT_ROWB + kt * 32);
        #pragma unroll
        for (int p = 0; p < 4; ++p)
            ldm_x4(bq[p], bBase + p * 16 * GT_ROWB + kt * 32);
        #pragma unroll
        for (int mt = 0; mt < 2; ++mt)
            #pragma unroll
            for (int p = 0; p < 4; ++p) {
                mma16816(acc[mt][2 * p],     af[mt], &bq[p][0]);
                mma16816(acc[mt][2 * p + 1], af[mt], &bq[p][2]);
            }
    }

    // ---- epilogue: scale, store, fused rowbest ----
    const float invden = 1.0f / DENOM_F;
    const int g = lane >> 2, tq = lane & 3;
    const int rowg = blockIdx.y * 128 + warpRow * 32 + g;
    const int colg = blockIdx.x * 128 + warpCol * 64 + tq * 2;

    #pragma unroll
    for (int mt = 0; mt < 2; ++mt) {
        int r0 = rowg + mt * 16;
        int r1 = r0 + 8;
        unsigned long long best0 = 0ull, best1 = 0ull;
        #pragma unroll
        for (int nt = 0; nt < 8; ++nt) {
            int col = colg + nt * 8;
            float2 v0, v1;
            v0.x = acc[mt][nt][0] * invden; v0.y = acc[mt][nt][1] * invden;
            v1.x = acc[mt][nt][2] * invden; v1.y = acc[mt][nt][3] * invden;
            *(float2*)(sim + (size_t)r0 * N_DET + col) = v0;
            *(float2*)(sim + (size_t)r1 * N_DET + col) = v1;
            unsigned long long k;
            k = ((unsigned long long)ordf(v0.x) << 32) | (unsigned)(~(unsigned)col);
            if (k > best0) best0 = k;
            k = ((unsigned long long)ordf(v0.y) << 32) | (unsigned)(~(unsigned)(col + 1));
            if (k > best0) best0 = k;
            k = ((unsigned long long)ordf(v1.x) << 32) | (unsigned)(~(unsigned)col);
            if (k > best1) best1 = k;
            k = ((unsigned long long)ordf(v1.y) << 32) | (unsigned)(~(unsigned)(col + 1));
            if (k > best1) best1 = k;
        }
        #pragma unroll
        for (int off = 1; off < 4; off <<= 1) {
            unsigned long long o0 = __shfl_xor_sync(0xFFFFFFFFu, best0, off);
            unsigned long long o1 = __shfl_xor_sync(0xFFFFFFFFu, best1, off);
            if (o0 > best0) best0 = o0;
            if (o1 > best1) best1 = o1;
        }
        if (tq == 0) {
            atomicMax(&g_rowbest[r0], best0);
            atomicMax(&g_rowbest[r1], best1);
        }
    }
}

// ---------------------------------------------------------------------------
// Parallel greedy match (exact equivalent of the sequential scan).
// ---------------------------------------------------------------------------
__global__ void claim_kernel() {
    int i = blockIdx.x * blockDim.x + threadIdx.x;
    if (i >= N_DET) return;
    const unsigned ORD_THR = __float_as_uint(0.3f) | 0x80000000u;
    unsigned long long rb = g_rowbest[i];
    unsigned ordsim = (unsigned)(rb >> 32);
    if (ordsim > ORD_THR) {
        unsigned j = ~(unsigned)rb;
        unsigned long long claimkey = (rb & 0xFFFFFFFF00000000ull) | (unsigned)(~(unsigned)i);
        atomicMax(&g_colbest[j], claimkey);
    }
}

__global__ void resolve_kernel(float* __restrict__ matches) {
    int i = blockIdx.x * blockDim.x + threadIdx.x;
    if (i >= N_DET) return;
    const unsigned ORD_THR = __float_as_uint(0.3f) | 0x80000000u;
    unsigned long long rb = g_rowbest[i];
    unsigned ordsim = (unsigned)(rb >> 32);
    float m = -1.0f;
    if (ordsim > ORD_THR) {
        unsigned j = ~(unsigned)rb;
        unsigned long long claimkey = (rb & 0xFFFFFFFF00000000ull) | (unsigned)(~(unsigned)i);
        if (g_colbest[j] == claimkey) m = (float)j;
    }
    matches[i] = m;
}

// ---------------------------------------------------------------------------
extern "C" void kernel_launch(void* const* d_in, const int* in_sizes, int n_in,
                              void* d_out, int out_size) {
    const float* det_t  = (const float*)d_in[0];
    const float* det_t1 = (const float*)d_in[1];
    const float* Wp1 = (const float*)d_in[2];
    const float* bp1 = (const float*)d_in[3];
    const float* Wp2 = (const float*)d_in[4];
    const float* bp2 = (const float*)d_in[5];
    const float* Wa1 = (const float*)d_in[6];
    const float* ba1 = (const float*)d_in[7];
    const float* Wa2 = (const float*)d_in[8];
    const float* ba2 = (const float*)d_in[9];
    float* out = (float*)d_out;                 // [0,4096): matches, then sim

    cudaFuncSetAttribute(encode_kernel, cudaFuncAttributeMaxDynamicSharedMemorySize,
                         ENC_SMEM_FLOATS * 4);
    cudaFuncSetAttribute(gemm_kernel, cudaFuncAttributeMaxDynamicSharedMemorySize,
                         GT_SMEM_TOTAL);

    init_kernel<<<16, 256>>>();
    encode_kernel<<<128, 256, ENC_SMEM_FLOATS * 4>>>(det_t, det_t1,
                                                     Wp1, bp1, Wp2, bp2,
                                                     Wa1, ba1, Wa2, ba2);
    evolve_kernel<<<512, 256>>>();
    gemm_kernel<<<dim3(32, 32), 256, GT_SMEM_TOTAL>>>(out + N_DET);
    claim_kernel<<<32, 128>>>();
    resolve_kernel<<<32, 128>>>(out);
}

// round 13
// speedup vs baseline: 1.4380x; 1.0589x over previous
#include <cuda_runtime.h>
#include <cuda_bf16.h>
#include <cstdint>

// ---------------------------------------------------------------------------
// PhaseTracker: encode(+init) -> evolve -> HMMA bf16-split GEMM -> match
// ---------------------------------------------------------------------------

#define N_DET   4096
#define DIM     128
#define HID     64
#define NOSC    28
#define KGEMM   192          // 3 blocks of 56 (hi|hi|lo vs hi|lo|hi) padded
#define KTILES  11           // k < 176 (data ends at 168, [168,176) zeroed)
#define TWO_PI_F 6.283185307179586f
#define INV_2PI  0.15915494309189535f
#define DENOM_F  28.000010583006244f   // (sqrt(28)+1e-6)^2

__device__ float g_phase[N_DET * NOSC];
__device__ float g_amp[N_DET * NOSC];
__device__ __align__(16) __nv_bfloat16 g_Abf[N_DET * KGEMM];  // [hi56|hi56|lo56|pad]
__device__ __align__(16) __nv_bfloat16 g_Bbf[N_DET * KGEMM];  // [hi56|lo56|hi56|pad]
__device__ unsigned long long g_rowbest[N_DET];
__device__ unsigned long long g_colbest[N_DET];
__device__ int g_bar1;
__device__ int g_bar2;

__device__ __forceinline__ float mod2pi(float v) {
    return v - floorf(v * INV_2PI) * TWO_PI_F;
}
__device__ __forceinline__ float softplusf(float x) {
    return fmaxf(x, 0.0f) + log1pf(expf(-fabsf(x)));
}
__device__ __forceinline__ unsigned ordf(float x) {
    unsigned u = __float_as_uint(x);
    return (u & 0x80000000u) ? ~u : (u | 0x80000000u);
}
__device__ __forceinline__ void bf16split(float v, __nv_bfloat16& hi, __nv_bfloat16& lo) {
    hi = __float2bfloat16_rn(v);
    lo = __float2bfloat16_rn(v - __bfloat162float(hi));
}
__device__ __forceinline__ uint32_t smem_u32(const void* p) {
    uint32_t a;
    asm("{ .reg .u64 t; cvta.to.shared.u64 t, %1; cvt.u32.u64 %0, t; }" : "=r"(a) : "l"(p));
    return a;
}
__device__ __forceinline__ void ldm_x4(uint32_t* r, uint32_t addr) {
    asm volatile("ldmatrix.sync.aligned.m8n8.x4.shared.b16 {%0,%1,%2,%3}, [%4];"
                 : "=r"(r[0]), "=r"(r[1]), "=r"(r[2]), "=r"(r[3]) : "r"(addr));
}
__device__ __forceinline__ void mma16816(float* c, const uint32_t* a, const uint32_t* b) {
    asm volatile("mma.sync.aligned.m16n8k16.row.col.f32.bf16.bf16.f32 "
                 "{%0,%1,%2,%3}, {%4,%5,%6,%7}, {%8,%9}, {%0,%1,%2,%3};"
                 : "+f"(c[0]), "+f"(c[1]), "+f"(c[2]), "+f"(c[3])
                 : "r"(a[0]), "r"(a[1]), "r"(a[2]), "r"(a[3]), "r"(b[0]), "r"(b[1]));
}

// ---------------------------------------------------------------------------
// Encode: EIGHT rows per thread per weight read; init fused into blocks 0-15.
// 128 blocks x 256 threads, 4 iterations of 16 rows.
// ---------------------------------------------------------------------------
#define ENC_W1STR 132
#define ENC_W2STR 68
#define ENC_SMEM_FLOATS (2*HID*ENC_W1STR + 2*NOSC*ENC_W2STR + 2048 + 2048)

__global__ __launch_bounds__(256, 2)
void encode_kernel(const float* __restrict__ det_t, const float* __restrict__ det_t1,
                   const float* __restrict__ Wp1, const float* __restrict__ bp1,
                   const float* __restrict__ Wp2, const float* __restrict__ bp2,
                   const float* __restrict__ Wa1, const float* __restrict__ ba1,
                   const float* __restrict__ Wa2, const float* __restrict__ ba2) {
    extern __shared__ float sm[];
    float* wp1T = sm;
    float* wa1T = wp1T + HID * ENC_W1STR;
    float* wp2T = wa1T + HID * ENC_W1STR;
    float* wa2T = wp2T + NOSC * ENC_W2STR;
    float* xs   = wa2T + NOSC * ENC_W2STR;     // 16 x 128
    float* hs   = xs + 2048;                   // 16 x 128

    int tid = threadIdx.x;

    // fused init (blocks 0..15): disjoint from all encode writes
    if (blockIdx.x < 16) {
        int i = blockIdx.x * 256 + tid;
        g_rowbest[i] = 0ull; g_colbest[i] = 0ull;
        uint4 z = make_uint4(0, 0, 0, 0);
        uint4* pa = (uint4*)((char*)g_Abf + (size_t)i * 384 + 336);
        uint4* pb = (uint4*)((char*)g_Bbf + (size_t)i * 384 + 336);
        pa[0] = z; pa[1] = z; pa[2] = z;
        pb[0] = z; pb[1] = z; pb[2] = z;
        if (i == 0) { g_bar1 = 0; g_bar2 = 0; }
    }

    for (int idx = tid; idx < DIM * HID; idx += 256) {
        int k = idx >> 6, j = idx & 63;
        wp1T[j * ENC_W1STR + k] = Wp1[idx];
        wa1T[j * ENC_W1STR + k] = Wa1[idx];
    }
    for (int idx = tid; idx < HID * NOSC; idx += 256) {
        int k = idx / NOSC, j = idx % NOSC;
        wp2T[j * ENC_W2STR + k] = Wp2[idx];
        wa2T[j * ENC_W2STR + k] = Wa2[idx];
    }

    const int quad = tid >> 7;
    const int t    = tid & 127;
    const int rb0  = 8 * quad;                 // local rows rb0..rb0+7

    for (int it = 0; it < 4; ++it) {
        int rowbase = blockIdx.x * 64 + it * 16;
        bool isT = rowbase < N_DET;
        const float* X = isT ? (det_t + (size_t)rowbase * DIM)
                             : (det_t1 + (size_t)(rowbase - N_DET) * DIM);
        __syncthreads();
        {
            const float4* s4 = (const float4*)X;
            float4* x4 = (float4*)xs;
            x4[tid] = s4[tid];
            x4[tid + 256] = s4[tid + 256];     // 16 rows x 128 floats
        }
        __syncthreads();

        // ---- layer 1: 8 rows per thread ----
        {
            bool doAmp = (t >= 64);
            if (!doAmp || isT) {
                int j = doAmp ? (t - 64) : t;
                const float4* w4 = (const float4*)(doAmp ? &wa1T[j * ENC_W1STR]
                                                         : &wp1T[j * ENC_W1STR]);
                const float4* xp[8];
                float a[8];
                float b = doAmp ? ba1[j] : bp1[j];
                #pragma unroll
                for (int r = 0; r < 8; ++r) {
                    xp[r] = (const float4*)(xs + (rb0 + r) * 128);
                    a[r] = b;
                }
                #pragma unroll
                for (int k4 = 0; k4 < 32; ++k4) {
                    float4 w = w4[k4];
                    #pragma unroll
                    for (int r = 0; r < 8; ++r) {
                        float4 v = xp[r][k4];
                        a[r] += w.x * v.x + w.y * v.y + w.z * v.z + w.w * v.w;
                    }
                }
                #pragma unroll
                for (int r = 0; r < 8; ++r)
                    hs[(rb0 + r) * 128 + t] = fmaxf(a[r], 0.0f);
            }
        }
        __syncthreads();

        // ---- layer 2: 8 rows per thread ----
        int lane = t & 31, wgrp = t >> 5;
        if (wgrp == 0 && lane < NOSC) {               // phase head
            const float4* w4 = (const float4*)&wp2T[lane * ENC_W2STR];
            const float4* hp[8];
            float p[8];
            float b = bp2[lane];
            #pragma unroll
            for (int r = 0; r < 8; ++r) {
                hp[r] = (const float4*)(hs + (rb0 + r) * 128);
                p[r] = b;
            }
            #pragma unroll
            for (int k4 = 0; k4 < 16; ++k4) {
                float4 w = w4[k4];
                #pragma unroll
                for (int r = 0; r < 8; ++r) {
                    float4 v = hp[r][k4];
                    p[r] += w.x * v.x + w.y * v.y + w.z * v.z + w.w * v.w;
                }
            }
            if (isT) {
                #pragma unroll
                for (int r = 0; r < 8; ++r)
                    g_phase[(rowbase + rb0 + r) * NOSC + lane] = mod2pi(p[r]);
            } else {
                // B' row layout: [cos_hi28 sin_hi28 | cos_lo28 sin_lo28 | cos_hi28 sin_hi28]
                #pragma unroll
                for (int r = 0; r < 8; ++r) {
                    int cc = rowbase - N_DET + rb0 + r;
                    float ph = mod2pi(p[r]);
                    float cv = cosf(ph), sv = sinf(ph);
                    __nv_bfloat16 chi, clo, shi, slo;
                    bf16split(cv, chi, clo); bf16split(sv, shi, slo);
                    __nv_bfloat16* br = g_Bbf + (size_t)cc * KGEMM;
                    br[lane] = chi;       br[28 + lane] = shi;
                    br[56 + lane] = clo;  br[84 + lane] = slo;
                    br[112 + lane] = chi; br[140 + lane] = shi;
                }
            }
        } else if (wgrp == 1 && lane < NOSC && isT) { // amp head
            const float4* w4 = (const float4*)&wa2T[lane * ENC_W2STR];
            const float4* hp[8];
            float p[8];
            float b = ba2[lane];
            #pragma unroll
            for (int r = 0; r < 8; ++r) {
                hp[r] = (const float4*)(hs + (rb0 + r) * 128 + 64);   // +64 floats = ha
                p[r] = b;
            }
            #pragma unroll
            for (int k4 = 0; k4 < 16; ++k4) {
                float4 w = w4[k4];
                #pragma unroll
                for (int r = 0; r < 8; ++r) {
                    float4 v = hp[r][k4];
                    p[r] += w.x * v.x + w.y * v.y + w.z * v.z + w.w * v.w;
                }
            }
            #pragma unroll
            for (int r = 0; r < 8; ++r)
                g_amp[(rowbase + rb0 + r) * NOSC + lane] = softplusf(p[r]);
        }
    }
}

// ---------------------------------------------------------------------------
// Evolve (proven): 5 Kuramoto steps, one warp per row.
// ---------------------------------------------------------------------------
__global__ void evolve_kernel() {
    int gw   = (blockIdx.x * blockDim.x + threadIdx.x) >> 5;
    int lane = threadIdx.x & 31;
    if (gw >= N_DET) return;
    bool act = lane < NOSC;

    float ph = act ? g_phase[gw * NOSC + lane] : 0.0f;
    float am = act ? g_amp[gw * NOSC + lane] : 0.0f;
    float omega = TWO_PI_F * (lane < 4 ? 2.0f : (lane < 12 ? 6.0f : 40.0f));

    #pragma unroll
    for (int s = 0; s < 5; ++s) {
        float c  = act ? cosf(ph) : 0.0f;
        float sn = act ? sinf(ph) : 0.0f;
        float sc = c, ss = sn;
        #pragma unroll
        for (int off = 16; off; off >>= 1) {
            sc += __shfl_down_sync(0xFFFFFFFFu, sc, off);
            ss += __shfl_down_sync(0xFFFFFFFFu, ss, off);
        }
        sc = __shfl_sync(0xFFFFFFFFu, sc, 0);
        ss = __shfl_sync(0xFFFFFFFFu, ss, 0);
        float mc = sc / 28.0f, ms = ss / 28.0f;
        float coup = ms * c - mc * sn;
        ph = mod2pi(ph + 0.01f * (omega + am * coup));
    }
    if (act) {
        float c = cosf(ph), sn = sinf(ph);
        __nv_bfloat16 chi, clo, shi, slo;
        bf16split(c, chi, clo); bf16split(sn, shi, slo);
        __nv_bfloat16* ar = g_Abf + (size_t)gw * KGEMM;
        ar[lane] = chi;       ar[28 + lane] = shi;
        ar[56 + lane] = chi;  ar[84 + lane] = shi;
        ar[112 + lane] = clo; ar[140 + lane] = slo;
    }
}

// ---------------------------------------------------------------------------
// HMMA GEMM (R12-proven): 128x128 tile/CTA, 8 warps (4x2), warp = 32x64,
// 2 CTAs/SM. Fused rowbest epilogue.
// ---------------------------------------------------------------------------
#define GT_ROWB   368
#define GT_TILE   (128 * GT_ROWB)           // 47104
#define GT_SMEM_TOTAL (2 * GT_TILE)         // 94208

__global__ __launch_bounds__(256, 2)
void gemm_kernel(float* __restrict__ sim) {
    extern __shared__ char smg[];
    const int tid = threadIdx.x;
    const int lane = tid & 31;
    const int w = tid >> 5;
    const int warpRow = w & 3;        // 0..3  (32 rows each)
    const int warpCol = w >> 2;       // 0..1  (64 cols each)
    uint32_t smA = smem_u32(smg);
    uint32_t smB = smA + GT_TILE;

    {
        const uint4* srcA = (const uint4*)(g_Abf + (size_t)blockIdx.y * 128 * KGEMM);
        const uint4* srcB = (const uint4*)(g_Bbf + (size_t)blockIdx.x * 128 * KGEMM);
        #pragma unroll
        for (int i = 0; i < 22; ++i) {
            int idx = tid + i * 256;          // 0..5631
            int half = idx >= 2816;
            int e = half ? idx - 2816 : idx;
            int r = e / 22, q = e - r * 22;
            int off = r * GT_ROWB + q * 16;
            if (half) *(uint4*)(smg + GT_TILE + off) = srcB[r * 24 + q];
            else      *(uint4*)(smg + off) = srcA[r * 24 + q];
        }
    }
    __syncthreads();

    float acc[2][8][4];
    #pragma unroll
    for (int mt = 0; mt < 2; ++mt)
        #pragma unroll
        for (int nt = 0; nt < 8; ++nt)
            #pragma unroll
            for (int e = 0; e < 4; ++e) acc[mt][nt][e] = 0.0f;

    const uint32_t aBase = smA + (warpRow * 32 + (lane & 15)) * GT_ROWB + (lane >> 4) * 16;
    const uint32_t bBase = smB + (warpCol * 64 + (lane & 7) + (lane >> 4) * 8) * GT_ROWB
                               + ((lane >> 3) & 1) * 16;

    #pragma unroll 2
    for (int kt = 0; kt < KTILES; ++kt) {
        uint32_t af[2][4];
        uint32_t bq[4][4];
        #pragma unroll
        for (int mt = 0; mt < 2; ++mt)
            ldm_x4(af[mt], aBase + mt * 16 * GT_ROWB + kt * 32);
        #pragma unroll
        for (int p = 0; p < 4; ++p)
            ldm_x4(bq[p], bBase + p * 16 * GT_ROWB + kt * 32);
        #pragma unroll
        for (int mt = 0; mt < 2; ++mt)
            #pragma unroll
            for (int p = 0; p < 4; ++p) {
                mma16816(acc[mt][2 * p],     af[mt], &bq[p][0]);
                mma16816(acc[mt][2 * p + 1], af[mt], &bq[p][2]);
            }
    }

    const float invden = 1.0f / DENOM_F;
    const int g = lane >> 2, tq = lane & 3;
    const int rowg = blockIdx.y * 128 + warpRow * 32 + g;
    const int colg = blockIdx.x * 128 + warpCol * 64 + tq * 2;

    #pragma unroll
    for (int mt = 0; mt < 2; ++mt) {
        int r0 = rowg + mt * 16;
        int r1 = r0 + 8;
        unsigned long long best0 = 0ull, best1 = 0ull;
        #pragma unroll
        for (int nt = 0; nt < 8; ++nt) {
            int col = colg + nt * 8;
            float2 v0, v1;
            v0.x = acc[mt][nt][0] * invden; v0.y = acc[mt][nt][1] * invden;
            v1.x = acc[mt][nt][2] * invden; v1.y = acc[mt][nt][3] * invden;
            *(float2*)(sim + (size_t)r0 * N_DET + col) = v0;
            *(float2*)(sim + (size_t)r1 * N_DET + col) = v1;
            unsigned long long k;
            k = ((unsigned long long)ordf(v0.x) << 32) | (unsigned)(~(unsigned)col);
            if (k > best0) best0 = k;
            k = ((unsigned long long)ordf(v0.y) << 32) | (unsigned)(~(unsigned)(col + 1));
            if (k > best0) best0 = k;
            k = ((unsigned long long)ordf(v1.x) << 32) | (unsigned)(~(unsigned)col);
            if (k > best1) best1 = k;
            k = ((unsigned long long)ordf(v1.y) << 32) | (unsigned)(~(unsigned)(col + 1));
            if (k > best1) best1 = k;
        }
        #pragma unroll
        for (int off = 1; off < 4; off <<= 1) {
            unsigned long long o0 = __shfl_xor_sync(0xFFFFFFFFu, best0, off);
            unsigned long long o1 = __shfl_xor_sync(0xFFFFFFFFu, best1, off);
            if (o0 > best0) best0 = o0;
            if (o1 > best1) best1 = o1;
        }
        if (tq == 0) {
            atomicMax(&g_rowbest[r0], best0);
            atomicMax(&g_rowbest[r1], best1);
        }
    }
}

// ---------------------------------------------------------------------------
// Match: claim + software grid barrier + resolve, one kernel.
// 16 blocks x 256 threads — all co-resident, so the spin barrier is safe.
// Two counters: g_bar1 = arrive (spun on), g_bar2 = depart (gates reset, no
// one spins on it) -> no reset/spin race, replayable under CUDA graphs.
// ---------------------------------------------------------------------------
__global__ void match_kernel(float* __restrict__ matches) {
    int i = blockIdx.x * 256 + threadIdx.x;
    const unsigned ORD_THR = __float_as_uint(0.3f) | 0x80000000u;

    // ---- claim ----
    unsigned long long rb = g_rowbest[i];
    unsigned ordsim = (unsigned)(rb >> 32);
    unsigned long long claimkey = 0ull;
    unsigned j = 0;
    bool eligible = (ordsim > ORD_THR);
    if (eligible) {
        j = ~(unsigned)rb;
        claimkey = (rb & 0xFFFFFFFF00000000ull) | (unsigned)(~(unsigned)i);
        atomicMax(&g_colbest[j], claimkey);
    }
    __threadfence();
    __syncthreads();

    // ---- grid barrier (arrive) ----
    if (threadIdx.x == 0) atomicAdd(&g_bar1, 1);
    while (*(volatile int*)&g_bar1 < 16) { }
    __threadfence();

    // ---- resolve own rows ----
    float m = -1.0f;
    if (eligible && g_colbest[j] == claimkey) m = (float)j;
    matches[i] = m;

    // ---- depart + reset (last block resets both counters) ----
    __syncthreads();
    if (threadIdx.x == 0) {
        int old = atomicAdd(&g_bar2, 1);
        if (old == 15) { g_bar1 = 0; g_bar2 = 0; }
    }
}

// ---------------------------------------------------------------------------
extern "C" void kernel_launch(void* const* d_in, const int* in_sizes, int n_in,
                              void* d_out, int out_size) {
    const float* det_t  = (const float*)d_in[0];
    const float* det_t1 = (const float*)d_in[1];
    const float* Wp1 = (const float*)d_in[2];
    const float* bp1 = (const float*)d_in[3];
    const float* Wp2 = (const float*)d_in[4];
    const float* bp2 = (const float*)d_in[5];
    const float* Wa1 = (const float*)d_in[6];
    const float* ba1 = (const float*)d_in[7];
    const float* Wa2 = (const float*)d_in[8];
    const float* ba2 = (const float*)d_in[9];
    float* out = (float*)d_out;                 // [0,4096): matches, then sim

    cudaFuncSetAttribute(encode_kernel, cudaFuncAttributeMaxDynamicSharedMemorySize,
                         ENC_SMEM_FLOATS * 4);
    cudaFuncSetAttribute(gemm_kernel, cudaFuncAttributeMaxDynamicSharedMemorySize,
                         GT_SMEM_TOTAL);

    encode_kernel<<<128, 256, ENC_SMEM_FLOATS * 4>>>(det_t, det_t1,
                                                     Wp1, bp1, Wp2, bp2,
                                                     Wa1, ba1, Wa2, ba2);
    evolve_kernel<<<512, 256>>>();
    gemm_kernel<<<dim3(32, 32), 256, GT_SMEM_TOTAL>>>(out + N_DET);
    match_kernel<<<16, 256>>>(out);
}